// round 15
// baseline (speedup 1.0000x reference)
#include <cuda_runtime.h>
#include <cuda_bf16.h>
#include <math.h>

#define NS 100     // stocks
#define ND 20      // days
#define NT 30      // texts per day
#define HH 64      // hidden
#define GG 192     // 3*H
#define NHD 8      // GAT heads
#define FT 512     // text feature
#define FP 3       // price feature
#define MROWS 600  // ND*NT

#define WHS_PAD 65
#define WHS_ELEMS (GG * WHS_PAD)   // 12480 floats

// ---------------- scratch (device globals; no runtime allocation) ----------------
__device__ __nv_bfloat16 g_gi_bf[(size_t)NS * MROWS * GG];  // text GRU input projections (bf16)
__device__ float g_outs[(size_t)NS * ND * NT * HH];         // text GRU hidden states
__device__ float g_news[NS * ND * HH];
__device__ float g_pvec[NS * HH];
__device__ float g_tvec[NS * HH];
__device__ float g_feat[NS * HH];
__device__ float g_hgat[NHD * NS * HH];
__device__ float g_f1[NHD * NS];
__device__ float g_f2[NHD * NS];
__device__ float g_x2[NS * NHD * HH];

#define LOG2E 1.4426950408889634f

__device__ __forceinline__ float fexp2(float x) { float r; asm("ex2.approx.f32 %0,%1;" : "=f"(r) : "f"(x)); return r; }
__device__ __forceinline__ float frcp(float x)  { float r; asm("rcp.approx.f32 %0,%1;" : "=f"(r) : "f"(x)); return r; }
__device__ __forceinline__ float ftanh(float x) { float r; asm("tanh.approx.f32 %0,%1;" : "=f"(r) : "f"(x)); return r; }
__device__ __forceinline__ float fsig(float x)  { return fmaf(0.5f, ftanh(0.5f * x), 0.5f); }
__device__ __forceinline__ float fexp(float x)  { return fexp2(LOG2E * x); }
__device__ __forceinline__ float felu(float x)  { return (x > 0.f) ? x : (fexp(x) - 1.f); }

__device__ __forceinline__ unsigned smem_u32(const void* p) {
    return (unsigned)__cvta_generic_to_shared(p);
}

// coalesced stage of a [192,64] fp32 matrix into padded smem [192][65]
__device__ __forceinline__ void stage_w(const float* __restrict__ src, float* whs, int tid, int nthr)
{
    const float4* s4 = (const float4*)src;
    for (int idx = tid; idx < (GG * HH) / 4; idx += nthr) {
        const float4 v = s4[idx];
        const int base = idx * 4;
        const int row = base >> 6;
        const int col = base & 63;
        float* d = whs + row * WHS_PAD + col;
        d[0] = v.x; d[1] = v.y; d[2] = v.z; d[3] = v.w;
    }
}

#define MMA_TF32(c, a0, a1, a2, a3, b0, b1) \
    asm volatile("mma.sync.aligned.m16n8k8.row.col.f32.tf32.tf32.f32 " \
                 "{%0,%1,%2,%3},{%4,%5,%6,%7},{%8,%9},{%0,%1,%2,%3};" \
                 : "+f"((c)[0]), "+f"((c)[1]), "+f"((c)[2]), "+f"((c)[3]) \
                 : "r"(a0), "r"(a1), "r"(a2), "r"(a3), "r"(b0), "r"(b1))

#define LDSM4(r0, r1, r2, r3, addr) \
    asm volatile("ldmatrix.sync.aligned.m8n8.x4.shared.b16 {%0,%1,%2,%3},[%4];" \
                 : "=r"(r0), "=r"(r1), "=r"(r2), "=r"(r3) : "r"(addr))

// ============================================================================
// Kernel 1: tf32 tensor-core GEMM, 2-stage cp.async, occ 3, single launch.
//   Fragment loads via ldmatrix (tf32-as-b16-pairs): 5 ldmatrix per ks-group
//   instead of 28 scalar LDS.
// ============================================================================
#define GBM 64
#define GBK 32
#define GPAD 36
#define GA_STAGE (GBM * GPAD)
#define GB_STAGE (GG * GPAD)
#define GSTAGE (GA_STAGE + GB_STAGE)
#define GEMM2_SMEM (GSTAGE * 2 * 4)

#define CPA16(dst, src, pred) do {                                          \
    unsigned _ds = smem_u32(dst);                                           \
    int _sz = (pred) ? 16 : 0;                                              \
    asm volatile("cp.async.cg.shared.global [%0],[%1],16,%2;"               \
                 :: "r"(_ds), "l"(src), "r"(_sz));                          \
} while (0)
#define CPA_COMMIT() asm volatile("cp.async.commit_group;")
#define CPA_WAIT(n)  asm volatile("cp.async.wait_group %0;" :: "n"(n))

__global__ __launch_bounds__(256, 3) void k_gemm_tf32(
    const float* __restrict__ A, const float* __restrict__ W,
    const float* __restrict__ bih)
{
    extern __shared__ float smf[];
    const int s  = blockIdx.y;
    const int m0 = blockIdx.x * GBM;

    const float* Ab = A + (size_t)s * MROWS * FT;
    const float* Wb = W + (size_t)s * GG * FT;

    const int tid  = threadIdx.x;
    const int lane = tid & 31;
    const int warp = tid >> 5;
    const int wm   = (warp & 1) * 32;
    const int wn   = (warp >> 1) * 48;

    // ldmatrix per-lane offset (floats): row (lane&7) + 8*bit3, col 4*bit4
    const int lmoff = ((lane & 7) + ((lane >> 3) & 1) * 8) * GPAD + ((lane >> 4) << 2);

    float acc[2][6][4];
#pragma unroll
    for (int mi = 0; mi < 2; mi++)
#pragma unroll
        for (int j = 0; j < 6; j++)
#pragma unroll
            for (int v = 0; v < 4; v++) acc[mi][j][v] = 0.f;

    const int lr = tid >> 3;
    const int lc = (tid & 7) * 4;

    auto load_tile = [&](int kt, int stage) {
        const int k0 = kt * GBK;
        float* base = smf + stage * GSTAGE;
#pragma unroll
        for (int i = 0; i < 2; i++) {
            const int r = lr + 32 * i;
            const float* src = Ab + (size_t)(m0 + r) * FT + k0 + lc;
            CPA16(base + r * GPAD + lc, src, (m0 + r) < MROWS);
        }
#pragma unroll
        for (int i = 0; i < 6; i++) {
            const int r = lr + 32 * i;
            const float* src = Wb + (size_t)r * FT + k0 + lc;
            CPA16(base + GA_STAGE + r * GPAD + lc, src, true);
        }
        CPA_COMMIT();
    };

    const int NKT = FT / GBK;   // 16
    load_tile(0, 0);
    CPA_WAIT(0);
    __syncthreads();

    for (int kt = 0; kt < NKT; kt++) {
        const int cur = kt & 1;
        if (kt + 1 < NKT) load_tile(kt + 1, cur ^ 1);

        const float* As_ = smf + cur * GSTAGE;
        const float* Bs_ = As_ + GA_STAGE;
        const unsigned abase = smem_u32(As_) + ((wm * GPAD) + lmoff) * 4;
        const unsigned bbase = smem_u32(Bs_) + ((wn * GPAD) + lmoff) * 4;

#pragma unroll
        for (int ks = 0; ks < 4; ks++) {
            const int kb = ks * 8;
            unsigned a[2][4];
#pragma unroll
            for (int mi = 0; mi < 2; mi++) {
                const unsigned addr = abase + (mi * 16 * GPAD + kb) * 4;
                LDSM4(a[mi][0], a[mi][1], a[mi][2], a[mi][3], addr);
            }
            unsigned b[6][2];
#pragma unroll
            for (int nj = 0; nj < 3; nj++) {
                const unsigned addr = bbase + (nj * 16 * GPAD + kb) * 4;
                unsigned t0, t1, t2, t3;
                LDSM4(t0, t1, t2, t3, addr);
                b[2 * nj][0] = t0; b[2 * nj + 1][0] = t1;
                b[2 * nj][1] = t2; b[2 * nj + 1][1] = t3;
            }
#pragma unroll
            for (int mi = 0; mi < 2; mi++)
#pragma unroll
                for (int j = 0; j < 6; j++)
                    MMA_TF32(acc[mi][j], a[mi][0], a[mi][1], a[mi][2], a[mi][3],
                             b[j][0], b[j][1]);
        }
        __syncthreads();
        if (kt + 1 < NKT) {
            CPA_WAIT(0);
            __syncthreads();
        }
    }

#pragma unroll
    for (int mi = 0; mi < 2; mi++) {
        const int row0 = m0 + wm + mi * 16 + (lane >> 2);
#pragma unroll
        for (int j = 0; j < 6; j++) {
            const int col = wn + j * 8 + (lane & 3) * 2;
            const float b0 = bih[s * GG + col];
            const float b1 = bih[s * GG + col + 1];
            if (row0 < MROWS) {
                __nv_bfloat162 v = __float22bfloat162_rn(
                    make_float2(acc[mi][j][0] + b0, acc[mi][j][1] + b1));
                *(__nv_bfloat162*)(g_gi_bf + ((size_t)s * MROWS + row0) * GG + col) = v;
            }
            if (row0 + 8 < MROWS) {
                __nv_bfloat162 v = __float22bfloat162_rn(
                    make_float2(acc[mi][j][2] + b0, acc[mi][j][3] + b1));
                *(__nv_bfloat162*)(g_gi_bf + ((size_t)s * MROWS + row0 + 8) * GG + col) = v;
            }
        }
    }
}

// ============================================================================
// Attention pool, warp-count templated (NW warps): Wa-register-reuse
// ============================================================================
template <int STEPS, int NW>
__device__ __forceinline__ void pool_store(
    const float* outs, const float* hs, const float* wa_s,
    float* sc, float* __restrict__ dst)
{
    const int tid  = threadIdx.x;
    const int warp = tid >> 5;
    const int lane = tid & 31;
    constexpr int TL = (STEPS + NW - 1) / NW;

    float acc[TL][2];
#pragma unroll
    for (int tl = 0; tl < TL; tl++) { acc[tl][0] = 0.f; acc[tl][1] = 0.f; }

#pragma unroll 8
    for (int i = 0; i < HH; i++) {
        const float w0 = wa_s[i * HH + lane];
        const float w1 = wa_s[i * HH + 32 + lane];
#pragma unroll
        for (int tl = 0; tl < TL; tl++) {
            const int t = warp + NW * tl;
            if (t < STEPS) {
                const float o = outs[t * HH + i];
                acc[tl][0] = fmaf(o, w0, acc[tl][0]);
                acc[tl][1] = fmaf(o, w1, acc[tl][1]);
            }
        }
    }
#pragma unroll
    for (int tl = 0; tl < TL; tl++) {
        const int t = warp + NW * tl;
        if (t < STEPS) {
            float p = fmaf(ftanh(acc[tl][0]), hs[lane],
                           ftanh(acc[tl][1]) * hs[lane + 32]);
#pragma unroll
            for (int o = 16; o; o >>= 1) p += __shfl_xor_sync(0xffffffffu, p, o);
            if (lane == 0) sc[t] = p;
        }
    }
    __syncthreads();
    if (warp == 0) {
        const float v = (lane < STEPS) ? sc[lane] : -3.4e38f;
        float m = v;
#pragma unroll
        for (int o = 16; o; o >>= 1) m = fmaxf(m, __shfl_xor_sync(0xffffffffu, m, o));
        const float e = (lane < STEPS) ? fexp(v - m) : 0.f;
        float su = e;
#pragma unroll
        for (int o = 16; o; o >>= 1) su += __shfl_xor_sync(0xffffffffu, su, o);
        if (lane < STEPS) sc[lane] = e / su;
    }
    __syncthreads();
    if (tid < HH) {
        float a = 0.f;
#pragma unroll
        for (int t = 0; t < STEPS; t++) a = fmaf(sc[t], outs[t * HH + tid], a);
        dst[tid] = a;
    }
}

// ============================================================================
// Kernel 2a: TENSOR-CORE text GRU recurrence — one block per STOCK, 384 thr.
// ============================================================================
#define HP 25
#define GP 26
#define TCR_THREADS 384
#define TCR_SMEM ((WHS_ELEMS + HH * HP + GG * GP) * 4)

__global__ __launch_bounds__(TCR_THREADS) void k_text_rec_tc(
    const float* __restrict__ Whh, const float* __restrict__ bhh)
{
    extern __shared__ float dyn[];
    float* whs = dyn;                    // staging [192][65]
    float* hsm = whs + WHS_ELEMS;        // h  [64][HP]
    float* ghs = hsm + HH * HP;          // gh [192][GP]

    const int s    = blockIdx.x;
    const int tid  = threadIdx.x;
    const int warp = tid >> 5;           // 0..11
    const int lane = tid & 31;
    const int wm   = warp * 16;

    stage_w(Whh + (size_t)s * GG * HH, whs, tid, TCR_THREADS);
    for (int i = tid; i < HH * HP; i += TCR_THREADS) hsm[i] = 0.f;
    __syncthreads();

    unsigned afr[8][4];
#pragma unroll
    for (int kb = 0; kb < 8; kb++) {
        const int r = wm + (lane >> 2);
        const int c = kb * 8 + (lane & 3);
        afr[kb][0] = __float_as_uint(whs[(r + 0) * WHS_PAD + c + 0]);
        afr[kb][1] = __float_as_uint(whs[(r + 8) * WHS_PAD + c + 0]);
        afr[kb][2] = __float_as_uint(whs[(r + 0) * WHS_PAD + c + 4]);
        afr[kb][3] = __float_as_uint(whs[(r + 8) * WHS_PAD + c + 4]);
    }
    const float bias0 = bhh[s * GG + wm + (lane >> 2)];
    const float bias1 = bhh[s * GG + wm + 8 + (lane >> 2)];

    const __nv_bfloat16* gib = g_gi_bf + (size_t)s * ND * NT * GG;

    float cur0[4], cur1[4], cur2[4];
    float pre0[4], pre1[4], pre2[4];
#pragma unroll
    for (int k = 0; k < 4; k++) {
        const int p = tid + TCR_THREADS * k;
        if (p < ND * HH) {
            const int d = p >> 6, j = p & 63;
            const __nv_bfloat16* gp = gib + ((size_t)d * NT) * GG + j;
            pre0[k] = __bfloat162float(gp[0]);
            pre1[k] = __bfloat162float(gp[64]);
            pre2[k] = __bfloat162float(gp[128]);
        }
    }

    for (int t = 0; t < NT; t++) {
        float acc[3][4];
#pragma unroll
        for (int nt = 0; nt < 3; nt++) {
            acc[nt][0] = bias0; acc[nt][1] = bias0;
            acc[nt][2] = bias1; acc[nt][3] = bias1;
        }
#pragma unroll
        for (int kb = 0; kb < 8; kb++) {
            unsigned bfr[3][2];
            const int k = kb * 8 + (lane & 3);
#pragma unroll
            for (int nt = 0; nt < 3; nt++) {
                const int n = nt * 8 + (lane >> 2);
                bfr[nt][0] = __float_as_uint(hsm[(k + 0) * HP + n]);
                bfr[nt][1] = __float_as_uint(hsm[(k + 4) * HP + n]);
            }
#pragma unroll
            for (int nt = 0; nt < 3; nt++)
                MMA_TF32(acc[nt], afr[kb][0], afr[kb][1], afr[kb][2], afr[kb][3],
                         bfr[nt][0], bfr[nt][1]);
        }
#pragma unroll
        for (int nt = 0; nt < 3; nt++) {
            const int r = wm + (lane >> 2);
            const int d = nt * 8 + (lane & 3) * 2;
            *(float2*)&ghs[(r + 0) * GP + d] = make_float2(acc[nt][0], acc[nt][1]);
            *(float2*)&ghs[(r + 8) * GP + d] = make_float2(acc[nt][2], acc[nt][3]);
        }
        __syncthreads();

#pragma unroll
        for (int k = 0; k < 4; k++) { cur0[k] = pre0[k]; cur1[k] = pre1[k]; cur2[k] = pre2[k]; }
        if (t + 1 < NT) {
#pragma unroll
            for (int k = 0; k < 4; k++) {
                const int p = tid + TCR_THREADS * k;
                if (p < ND * HH) {
                    const int d = p >> 6, j = p & 63;
                    const __nv_bfloat16* gp = gib + ((size_t)d * NT + (t + 1)) * GG + j;
                    pre0[k] = __bfloat162float(gp[0]);
                    pre1[k] = __bfloat162float(gp[64]);
                    pre2[k] = __bfloat162float(gp[128]);
                }
            }
        }

#pragma unroll
        for (int k = 0; k < 4; k++) {
            const int p = tid + TCR_THREADS * k;
            if (p < ND * HH) {
                const int d = p >> 6, j = p & 63;
                const float r  = fsig(cur0[k] + ghs[j * GP + d]);
                const float z  = fsig(cur1[k] + ghs[(64 + j) * GP + d]);
                const float n  = ftanh(cur2[k] + r * ghs[(128 + j) * GP + d]);
                const float hp_ = hsm[j * HP + d];
                const float hn  = (1.f - z) * n + z * hp_;
                hsm[j * HP + d] = hn;
                g_outs[((size_t)(s * ND + d) * NT + t) * HH + j] = hn;
            }
        }
        __syncthreads();
    }
}

// ============================================================================
// Kernel 2b: text attention pooling — one block per (stock, day), 256 threads
// ============================================================================
__global__ __launch_bounds__(256) void k_text_pool(const float* __restrict__ Wa)
{
    __shared__ float outs_s[NT * HH];
    __shared__ float wa_s[HH * HH];
    __shared__ float sc[32];
    const int sd = blockIdx.x;
    const int s  = sd / ND;
    const int g  = threadIdx.x;

    const float4* src = (const float4*)(g_outs + (size_t)sd * NT * HH);
    for (int i = g; i < (NT * HH) / 4; i += 256) ((float4*)outs_s)[i] = src[i];
    const float4* wsrc = (const float4*)(Wa + (size_t)s * HH * HH);
    for (int i = g; i < (HH * HH) / 4; i += 256) ((float4*)wa_s)[i] = wsrc[i];
    __syncthreads();

    pool_store<NT, 8>(outs_s, outs_s + (NT - 1) * HH, wa_s, sc, g_news + (size_t)sd * HH);
}

// ============================================================================
// Kernel 3: generic per-stock GRU + pool; single staging phase (192 threads)
// ============================================================================
template <int IN, int STEPS, int SRC>
__global__ __launch_bounds__(192) void k_gru_pool(
    const float* __restrict__ xin,
    const float* __restrict__ Wih, const float* __restrict__ Whh,
    const float* __restrict__ bih, const float* __restrict__ bhh,
    const float* __restrict__ Wa)
{
    extern __shared__ float dyn[];
    float* whh_s = dyn;
    float* wih_s = whh_s + WHS_ELEMS;
    float* gis   = wih_s + (IN == HH ? WHS_ELEMS : 0);
    float* outs  = gis + STEPS * GG;
    float* wa_s  = outs + STEPS * HH;
    float* xs    = wa_s + HH * HH;
    float* hs    = xs + STEPS * IN;
    float* ghs   = hs + HH;
    float* sc    = ghs + GG;

    const int s = blockIdx.x;
    const int g = threadIdx.x;

    const float* xb = (SRC == 1) ? (g_news + (size_t)s * ND * HH)
                                 : (xin + (size_t)s * STEPS * IN);
    const float bh = bhh[s * GG + g];
    const float bi = bih[s * GG + g];

    for (int i = g; i < STEPS * IN; i += 192) xs[i] = xb[i];
    {
        const float4* src = (const float4*)(Wa + (size_t)s * HH * HH);
        for (int i = g; i < (HH * HH) / 4; i += 192) ((float4*)wa_s)[i] = src[i];
    }
    stage_w(Whh + (size_t)s * GG * HH, whh_s, g, 192);
    if (IN == HH) stage_w(Wih + (size_t)s * GG * IN, wih_s, g, 192);
    float wi[IN <= 4 ? IN : 1];
    if (IN != HH) {
        const float* wip = Wih + ((size_t)s * GG + g) * IN;
#pragma unroll
        for (int i = 0; i < IN; i++) wi[i] = wip[i];
    }
    if (g < HH) hs[g] = 0.f;
    __syncthreads();

    if (IN == HH) {
        float acct[STEPS];
#pragma unroll
        for (int t = 0; t < STEPS; t++) acct[t] = bi;
#pragma unroll 4
        for (int i = 0; i < IN; i++) {
            const float w = wih_s[g * WHS_PAD + i];
#pragma unroll
            for (int t = 0; t < STEPS; t++) acct[t] = fmaf(w, xs[t * IN + i], acct[t]);
        }
#pragma unroll
        for (int t = 0; t < STEPS; t++) gis[t * GG + g] = acct[t];
    } else {
#pragma unroll
        for (int t = 0; t < STEPS; t++) {
            float gi = bi;
#pragma unroll
            for (int i = 0; i < IN; i++) gi = fmaf(wi[i], xs[t * IN + i], gi);
            gis[t * GG + g] = gi;
        }
    }
    __syncthreads();

    float wh[HH];
#pragma unroll
    for (int i = 0; i < HH; i++) wh[i] = whh_s[g * WHS_PAD + i];

    for (int t = 0; t < STEPS; t++) {
        float a0 = 0.f, a1 = 0.f, a2 = 0.f, a3 = 0.f;
#pragma unroll
        for (int i = 0; i < HH; i += 4) {
            a0 = fmaf(wh[i + 0], hs[i + 0], a0);
            a1 = fmaf(wh[i + 1], hs[i + 1], a1);
            a2 = fmaf(wh[i + 2], hs[i + 2], a2);
            a3 = fmaf(wh[i + 3], hs[i + 3], a3);
        }
        ghs[g] = bh + ((a0 + a1) + (a2 + a3));
        __syncthreads();
        if (g < HH) {
            const float* git = gis + t * GG;
            const float r  = fsig(git[g] + ghs[g]);
            const float z  = fsig(git[HH + g] + ghs[HH + g]);
            const float n  = ftanh(git[2 * HH + g] + r * ghs[2 * HH + g]);
            const float hn = (1.f - z) * n + z * hs[g];
            hs[g] = hn;
            outs[t * HH + g] = hn;
        }
        __syncthreads();
    }
    float* dst = (SRC == 1 ? g_tvec : g_pvec) + s * HH;
    pool_store<STEPS, 6>(outs, hs, wa_s, sc, dst);
}

// ============================================================================
// Kernel 4: bilinear fusion
// ============================================================================
__global__ __launch_bounds__(128) void k_bilinear(
    const float* __restrict__ B, const float* __restrict__ bb)
{
    const int o = blockIdx.x, s = blockIdx.y;
    const int tid = threadIdx.x;
    __shared__ float tv_s[HH], pv_s[HH];
    if (tid < HH) { tv_s[tid] = g_tvec[s * HH + tid]; pv_s[tid] = g_pvec[s * HH + tid]; }
    __syncthreads();

    const float* Bp = B + ((size_t)s * HH + o) * HH * HH;
    float acc = 0.f;
#pragma unroll
    for (int it = 0; it < 8; it++) {
        const int k4 = (it * 128 + tid) * 4;
        const float4 v = *(const float4*)(Bp + k4);
        const int i = k4 >> 6, j = k4 & 63;
        float p = pv_s[j] * v.x;
        p = fmaf(pv_s[j + 1], v.y, p);
        p = fmaf(pv_s[j + 2], v.z, p);
        p = fmaf(pv_s[j + 3], v.w, p);
        acc = fmaf(tv_s[i], p, acc);
    }
    __shared__ float red[128];
    red[tid] = acc;
    __syncthreads();
    for (int st2 = 64; st2; st2 >>= 1) {
        if (tid < st2) red[tid] += red[tid + st2];
        __syncthreads();
    }
    if (tid == 0) g_feat[s * HH + o] = ftanh(red[0] + bb[s * HH + o]);
}

// ============================================================================
// Kernel 5: GAT head projection
// ============================================================================
__global__ __launch_bounds__(64) void k_gat_proj(
    const float* __restrict__ gatW, const float* __restrict__ gatA)
{
    const int s = blockIdx.x, nh = blockIdx.y;
    const int j = threadIdx.x;
    const float* Wp = gatW + (size_t)nh * HH * HH;
    const float* x  = g_feat + s * HH;
    float acc = 0.f;
#pragma unroll 8
    for (int i = 0; i < HH; i++) acc = fmaf(x[i], Wp[i * HH + j], acc);
    g_hgat[((size_t)nh * NS + s) * HH + j] = acc;

    __shared__ float r1[64], r2[64];
    r1[j] = acc * gatA[nh * 2 * HH + j];
    r2[j] = acc * gatA[nh * 2 * HH + HH + j];
    __syncthreads();
    if (j < 32) {
        float v1 = r1[j] + r1[j + 32];
        float v2 = r2[j] + r2[j + 32];
#pragma unroll
        for (int o = 16; o; o >>= 1) {
            v1 += __shfl_xor_sync(0xffffffffu, v1, o);
            v2 += __shfl_xor_sync(0xffffffffu, v2, o);
        }
        if (j == 0) { g_f1[nh * NS + s] = v1; g_f2[nh * NS + s] = v2; }
    }
}

// ============================================================================
// Kernel 6: GAT masked attention + elu
// ============================================================================
__global__ __launch_bounds__(128) void k_gat_attn(const float* __restrict__ adj)
{
    const int s = blockIdx.x, nh = blockIdx.y;
    const int tid = threadIdx.x;
    __shared__ float att[NS];
    __shared__ float sinv;
    const float f1v = g_f1[nh * NS + s];
    if (tid < NS) {
        float v = f1v + g_f2[nh * NS + tid];
        v = (v >= 0.f) ? v : 0.2f * v;
        att[tid] = (adj[s * NS + tid] > 0.f) ? v : -9e15f;
    }
    __syncthreads();
    if (tid < 32) {
        float m = -3.4e38f;
        for (int t = tid; t < NS; t += 32) m = fmaxf(m, att[t]);
#pragma unroll
        for (int o = 16; o; o >>= 1) m = fmaxf(m, __shfl_xor_sync(0xffffffffu, m, o));
        float su = 0.f;
        for (int t = tid; t < NS; t += 32) {
            const float e = fexp(att[t] - m);
            att[t] = e;
            su += e;
        }
#pragma unroll
        for (int o = 16; o; o >>= 1) su += __shfl_xor_sync(0xffffffffu, su, o);
        if (tid == 0) sinv = 1.f / su;
    }
    __syncthreads();
    if (tid < HH) {
        float acc = 0.f;
        for (int t = 0; t < NS; t++)
            acc = fmaf(att[t], g_hgat[((size_t)nh * NS + t) * HH + tid], acc);
        acc = felu(acc * sinv);
        g_x2[(size_t)s * (NHD * HH) + nh * HH + tid] = acc;
    }
}

// ============================================================================
// Kernel 7: final — out-layer GAT, blend, double softmax, loss. One block.
// ============================================================================
__global__ __launch_bounds__(128) void k_final(
    const float* __restrict__ blW, const float* __restrict__ blb,
    const float* __restrict__ outW, const float* __restrict__ outA,
    const float* __restrict__ adj, const int* __restrict__ label,
    float* __restrict__ out, int out_size)
{
    __shared__ float h2[NS][2];
    __shared__ float f1s[NS], f2s[NS];
    __shared__ float o1[NS][2];
    __shared__ float adj_s[NS * NS];
    __shared__ float red[128];
    const int tid  = threadIdx.x;
    const int warp = tid >> 5;
    const int lane = tid & 31;

    for (int i = tid; i < NS * NS; i += 128) adj_s[i] = adj[i];

    for (int s = warp; s < NS; s += 4) {
        const float* xr = g_x2 + (size_t)s * NHD * HH;
        float a0 = 0.f, a1 = 0.f;
        for (int k = lane; k < NHD * HH; k += 32) {
            const float xv = xr[k];
            a0 = fmaf(xv, outW[2 * k + 0], a0);
            a1 = fmaf(xv, outW[2 * k + 1], a1);
        }
        const float* fr = g_feat + s * HH;
        float b0 = 0.f, b1 = 0.f;
        for (int k = lane; k < HH; k += 32) {
            const float fv = fr[k];
            b0 = fmaf(fv, blW[2 * k + 0], b0);
            b1 = fmaf(fv, blW[2 * k + 1], b1);
        }
#pragma unroll
        for (int o = 16; o; o >>= 1) {
            a0 += __shfl_xor_sync(0xffffffffu, a0, o);
            a1 += __shfl_xor_sync(0xffffffffu, a1, o);
            b0 += __shfl_xor_sync(0xffffffffu, b0, o);
            b1 += __shfl_xor_sync(0xffffffffu, b1, o);
        }
        if (lane == 0) {
            h2[s][0] = a0; h2[s][1] = a1;
            f1s[s] = a0 * outA[0] + a1 * outA[1];
            f2s[s] = a0 * outA[2] + a1 * outA[3];
            o1[s][0] = ftanh(b0 + blb[0]);
            o1[s][1] = ftanh(b1 + blb[1]);
        }
    }
    __syncthreads();

    const int off = (out_size > 200) ? (out_size - 200) : 0;
    float lsum = 0.f;
    for (int s = tid; s < NS; s += 128) {
        float m = -3.4e38f;
        for (int t = 0; t < NS; t++) {
            float v = f1s[s] + f2s[t];
            v = (v >= 0.f) ? v : 0.2f * v;
            v = (adj_s[s * NS + t] > 0.f) ? v : -9e15f;
            m = fmaxf(m, v);
        }
        float su = 0.f, a0 = 0.f, a1 = 0.f;
        for (int t = 0; t < NS; t++) {
            float v = f1s[s] + f2s[t];
            v = (v >= 0.f) ? v : 0.2f * v;
            v = (adj_s[s * NS + t] > 0.f) ? v : -9e15f;
            const float e = fexp(v - m);
            su += e;
            a0 = fmaf(e, h2[t][0], a0);
            a1 = fmaf(e, h2[t][1], a1);
        }
        a0 /= su; a1 /= su;
        a0 = felu(a0);
        a1 = felu(a1);
        const float z0 = a0 + o1[s][0];
        const float z1 = a1 + o1[s][1];
        const float zm = fmaxf(z0, z1);
        const float e0 = fexp(z0 - zm), e1 = fexp(z1 - zm);
        const float p0 = e0 / (e0 + e1), p1 = e1 / (e0 + e1);
        if (out_size >= 200) { out[off + 2 * s] = p0; out[off + 2 * s + 1] = p1; }
        const float pm  = fmaxf(p0, p1);
        const float lse = pm + logf(fexp(p0 - pm) + fexp(p1 - pm));
        const float chosen = (label[s] == 0) ? p0 : p1;
        lsum += (lse - chosen);
    }
    red[tid] = lsum;
    __syncthreads();
    for (int st2 = 64; st2; st2 >>= 1) {
        if (tid < st2) red[tid] += red[tid + st2];
        __syncthreads();
    }
    if (tid == 0 && (out_size == 1 || out_size > 200)) out[0] = red[0] * (1.f / NS);
}

// ============================================================================
extern "C" void kernel_launch(void* const* d_in, const int* in_sizes, int n_in,
                              void* d_out, int out_size)
{
    (void)in_sizes;
    const float* text  = (const float*)d_in[0];
    const float* price = (const float*)d_in[1];
    const int*   label = (const int*)d_in[2];
    const float* adj   = (const float*)d_in[3];
    const int wb = n_in - 23;
    const float* pg_Wih = (const float*)d_in[wb + 0];
    const float* pg_Whh = (const float*)d_in[wb + 1];
    const float* pg_bih = (const float*)d_in[wb + 2];
    const float* pg_bhh = (const float*)d_in[wb + 3];
    const float* pa_W   = (const float*)d_in[wb + 4];
    const float* tg_Wih = (const float*)d_in[wb + 5];
    const float* tg_Whh = (const float*)d_in[wb + 6];
    const float* tg_bih = (const float*)d_in[wb + 7];
    const float* tg_bhh = (const float*)d_in[wb + 8];
    const float* ta_W   = (const float*)d_in[wb + 9];
    const float* sg_Wih = (const float*)d_in[wb + 10];
    const float* sg_Whh = (const float*)d_in[wb + 11];
    const float* sg_bih = (const float*)d_in[wb + 12];
    const float* sg_bhh = (const float*)d_in[wb + 13];
    const float* sa_W   = (const float*)d_in[wb + 14];
    const float* bil_B  = (const float*)d_in[wb + 15];
    const float* bil_b  = (const float*)d_in[wb + 16];
    const float* bl_W   = (const float*)d_in[wb + 17];
    const float* bl_b   = (const float*)d_in[wb + 18];
    const float* gat_W  = (const float*)d_in[wb + 19];
    const float* gat_a  = (const float*)d_in[wb + 20];
    const float* out_W  = (const float*)d_in[wb + 21];
    const float* out_a  = (const float*)d_in[wb + 22];

    const int smem_gru64 = (2 * WHS_ELEMS + ND * GG + ND * HH + HH * HH + ND * HH + HH + GG + 32) * 4;
    const int smem_gru3  = (WHS_ELEMS + ND * GG + ND * HH + HH * HH + ND * FP + HH + GG + 32) * 4;

    static cudaStream_t s2 = nullptr;
    static cudaEvent_t evA = nullptr, evB = nullptr;
    if (!s2) {
        cudaFuncSetAttribute(k_gemm_tf32,
                             cudaFuncAttributeMaxDynamicSharedMemorySize, GEMM2_SMEM);
        cudaFuncSetAttribute(k_text_rec_tc,
                             cudaFuncAttributeMaxDynamicSharedMemorySize, TCR_SMEM);
        cudaFuncSetAttribute((const void*)k_gru_pool<HH, ND, 1>,
                             cudaFuncAttributeMaxDynamicSharedMemorySize, smem_gru64);
        cudaFuncSetAttribute((const void*)k_gru_pool<FP, ND, 0>,
                             cudaFuncAttributeMaxDynamicSharedMemorySize, smem_gru3);
        cudaStreamCreateWithFlags(&s2, cudaStreamNonBlocking);
        cudaEventCreateWithFlags(&evA, cudaEventDisableTiming);
        cudaEventCreateWithFlags(&evB, cudaEventDisableTiming);
    }

    // fork: price path runs concurrently with the text path
    cudaEventRecord(evA, 0);
    cudaStreamWaitEvent(s2, evA, 0);
    k_gru_pool<FP, ND, 0><<<NS, 192, smem_gru3, s2>>>(price, pg_Wih, pg_Whh, pg_bih, pg_bhh, pa_W);
    cudaEventRecord(evB, s2);

    // text path (main stream)
    k_gemm_tf32<<<dim3(10, NS), 256, GEMM2_SMEM>>>(text, tg_Wih, tg_bih);
    k_text_rec_tc<<<NS, TCR_THREADS, TCR_SMEM>>>(tg_Whh, tg_bhh);
    k_text_pool<<<NS * ND, 256>>>(ta_W);
    k_gru_pool<HH, ND, 1><<<NS, 192, smem_gru64>>>(nullptr, sg_Wih, sg_Whh, sg_bih, sg_bhh, sa_W);

    // join price path, then fusion + GAT + output
    cudaStreamWaitEvent(0, evB, 0);
    k_bilinear<<<dim3(HH, NS), 128>>>(bil_B, bil_b);
    k_gat_proj<<<dim3(NS, NHD), 64>>>(gat_W, gat_a);
    k_gat_attn<<<dim3(NS, NHD), 128>>>(adj);
    k_final<<<1, 128>>>(bl_W, bl_b, out_W, out_a, adj, label, (float*)d_out, out_size);
}

// round 16
// speedup vs baseline: 1.0064x; 1.0064x over previous
#include <cuda_runtime.h>
#include <cuda_bf16.h>
#include <math.h>

#define NS 100     // stocks
#define ND 20      // days
#define NT 30      // texts per day
#define HH 64      // hidden
#define GG 192     // 3*H
#define NHD 8      // GAT heads
#define FT 512     // text feature
#define FP 3       // price feature
#define MROWS 600  // ND*NT

#define WHS_PAD 65
#define WHS_ELEMS (GG * WHS_PAD)   // 12480 floats

// ---------------- scratch (device globals; no runtime allocation) ----------------
__device__ __nv_bfloat16 g_gi_bf[(size_t)NS * MROWS * GG];  // text GRU input projections (bf16)
__device__ float g_outs[(size_t)NS * ND * NT * HH];         // text GRU hidden states
__device__ float g_news[NS * ND * HH];
__device__ float g_pvec[NS * HH];
__device__ float g_tvec[NS * HH];
__device__ float g_feat[NS * HH];
__device__ float g_hgat[NHD * NS * HH];
__device__ float g_f1[NHD * NS];
__device__ float g_f2[NHD * NS];
__device__ float g_x2[NS * NHD * HH];

#define LOG2E 1.4426950408889634f

__device__ __forceinline__ float fexp2(float x) { float r; asm("ex2.approx.f32 %0,%1;" : "=f"(r) : "f"(x)); return r; }
__device__ __forceinline__ float frcp(float x)  { float r; asm("rcp.approx.f32 %0,%1;" : "=f"(r) : "f"(x)); return r; }
__device__ __forceinline__ float ftanh(float x) { float r; asm("tanh.approx.f32 %0,%1;" : "=f"(r) : "f"(x)); return r; }
__device__ __forceinline__ float fsig(float x)  { return fmaf(0.5f, ftanh(0.5f * x), 0.5f); }
__device__ __forceinline__ float fexp(float x)  { return fexp2(LOG2E * x); }
__device__ __forceinline__ float felu(float x)  { return (x > 0.f) ? x : (fexp(x) - 1.f); }

__device__ __forceinline__ unsigned smem_u32(const void* p) {
    return (unsigned)__cvta_generic_to_shared(p);
}

// coalesced stage of a [192,64] fp32 matrix into padded smem [192][65]
__device__ __forceinline__ void stage_w(const float* __restrict__ src, float* whs, int tid, int nthr)
{
    const float4* s4 = (const float4*)src;
    for (int idx = tid; idx < (GG * HH) / 4; idx += nthr) {
        const float4 v = s4[idx];
        const int base = idx * 4;
        const int row = base >> 6;
        const int col = base & 63;
        float* d = whs + row * WHS_PAD + col;
        d[0] = v.x; d[1] = v.y; d[2] = v.z; d[3] = v.w;
    }
}

#define MMA_TF32(c, a0, a1, a2, a3, b0, b1) \
    asm volatile("mma.sync.aligned.m16n8k8.row.col.f32.tf32.tf32.f32 " \
                 "{%0,%1,%2,%3},{%4,%5,%6,%7},{%8,%9},{%0,%1,%2,%3};" \
                 : "+f"((c)[0]), "+f"((c)[1]), "+f"((c)[2]), "+f"((c)[3]) \
                 : "r"(a0), "r"(a1), "r"(a2), "r"(a3), "r"(b0), "r"(b1))

#define LDSM4(r0, r1, r2, r3, addr) \
    asm volatile("ldmatrix.sync.aligned.m8n8.x4.shared.b16 {%0,%1,%2,%3},[%4];" \
                 : "=r"(r0), "=r"(r1), "=r"(r2), "=r"(r3) : "r"(addr))

// ============================================================================
// Kernel 1: tf32 tensor-core GEMM, 2-stage cp.async, occ 3, single launch.
//   Fragment loads via ldmatrix (tf32-as-b16-pairs): 5 ldmatrix per ks-group
//   instead of 28 scalar LDS.
// ============================================================================
#define GBM 64
#define GBK 32
#define GPAD 36
#define GA_STAGE (GBM * GPAD)
#define GB_STAGE (GG * GPAD)
#define GSTAGE (GA_STAGE + GB_STAGE)
#define GEMM2_SMEM (GSTAGE * 2 * 4)

#define CPA16(dst, src, pred) do {                                          \
    unsigned _ds = smem_u32(dst);                                           \
    int _sz = (pred) ? 16 : 0;                                              \
    asm volatile("cp.async.cg.shared.global [%0],[%1],16,%2;"               \
                 :: "r"(_ds), "l"(src), "r"(_sz));                          \
} while (0)
#define CPA_COMMIT() asm volatile("cp.async.commit_group;")
#define CPA_WAIT(n)  asm volatile("cp.async.wait_group %0;" :: "n"(n))

__global__ __launch_bounds__(256, 3) void k_gemm_tf32(
    const float* __restrict__ A, const float* __restrict__ W,
    const float* __restrict__ bih)
{
    extern __shared__ float smf[];
    const int s  = blockIdx.y;
    const int m0 = blockIdx.x * GBM;

    const float* Ab = A + (size_t)s * MROWS * FT;
    const float* Wb = W + (size_t)s * GG * FT;

    const int tid  = threadIdx.x;
    const int lane = tid & 31;
    const int warp = tid >> 5;
    const int wm   = (warp & 1) * 32;
    const int wn   = (warp >> 1) * 48;

    // ldmatrix per-lane offset (floats): row (lane&7) + 8*bit3, col 4*bit4
    const int lmoff = ((lane & 7) + ((lane >> 3) & 1) * 8) * GPAD + ((lane >> 4) << 2);

    float acc[2][6][4];
#pragma unroll
    for (int mi = 0; mi < 2; mi++)
#pragma unroll
        for (int j = 0; j < 6; j++)
#pragma unroll
            for (int v = 0; v < 4; v++) acc[mi][j][v] = 0.f;

    const int lr = tid >> 3;
    const int lc = (tid & 7) * 4;

    auto load_tile = [&](int kt, int stage) {
        const int k0 = kt * GBK;
        float* base = smf + stage * GSTAGE;
#pragma unroll
        for (int i = 0; i < 2; i++) {
            const int r = lr + 32 * i;
            const float* src = Ab + (size_t)(m0 + r) * FT + k0 + lc;
            CPA16(base + r * GPAD + lc, src, (m0 + r) < MROWS);
        }
#pragma unroll
        for (int i = 0; i < 6; i++) {
            const int r = lr + 32 * i;
            const float* src = Wb + (size_t)r * FT + k0 + lc;
            CPA16(base + GA_STAGE + r * GPAD + lc, src, true);
        }
        CPA_COMMIT();
    };

    const int NKT = FT / GBK;   // 16
    load_tile(0, 0);
    CPA_WAIT(0);
    __syncthreads();

    for (int kt = 0; kt < NKT; kt++) {
        const int cur = kt & 1;
        if (kt + 1 < NKT) load_tile(kt + 1, cur ^ 1);

        const float* As_ = smf + cur * GSTAGE;
        const float* Bs_ = As_ + GA_STAGE;
        const unsigned abase = smem_u32(As_) + ((wm * GPAD) + lmoff) * 4;
        const unsigned bbase = smem_u32(Bs_) + ((wn * GPAD) + lmoff) * 4;

#pragma unroll
        for (int ks = 0; ks < 4; ks++) {
            const int kb = ks * 8;
            unsigned a[2][4];
#pragma unroll
            for (int mi = 0; mi < 2; mi++) {
                const unsigned addr = abase + (mi * 16 * GPAD + kb) * 4;
                LDSM4(a[mi][0], a[mi][1], a[mi][2], a[mi][3], addr);
            }
            unsigned b[6][2];
#pragma unroll
            for (int nj = 0; nj < 3; nj++) {
                const unsigned addr = bbase + (nj * 16 * GPAD + kb) * 4;
                unsigned t0, t1, t2, t3;
                LDSM4(t0, t1, t2, t3, addr);
                b[2 * nj][0] = t0; b[2 * nj + 1][0] = t1;
                b[2 * nj][1] = t2; b[2 * nj + 1][1] = t3;
            }
#pragma unroll
            for (int mi = 0; mi < 2; mi++)
#pragma unroll
                for (int j = 0; j < 6; j++)
                    MMA_TF32(acc[mi][j], a[mi][0], a[mi][1], a[mi][2], a[mi][3],
                             b[j][0], b[j][1]);
        }
        __syncthreads();
        if (kt + 1 < NKT) {
            CPA_WAIT(0);
            __syncthreads();
        }
    }

#pragma unroll
    for (int mi = 0; mi < 2; mi++) {
        const int row0 = m0 + wm + mi * 16 + (lane >> 2);
#pragma unroll
        for (int j = 0; j < 6; j++) {
            const int col = wn + j * 8 + (lane & 3) * 2;
            const float b0 = bih[s * GG + col];
            const float b1 = bih[s * GG + col + 1];
            if (row0 < MROWS) {
                __nv_bfloat162 v = __float22bfloat162_rn(
                    make_float2(acc[mi][j][0] + b0, acc[mi][j][1] + b1));
                *(__nv_bfloat162*)(g_gi_bf + ((size_t)s * MROWS + row0) * GG + col) = v;
            }
            if (row0 + 8 < MROWS) {
                __nv_bfloat162 v = __float22bfloat162_rn(
                    make_float2(acc[mi][j][2] + b0, acc[mi][j][3] + b1));
                *(__nv_bfloat162*)(g_gi_bf + ((size_t)s * MROWS + row0 + 8) * GG + col) = v;
            }
        }
    }
}

// ============================================================================
// Attention pool, warp-count templated (NW warps): Wa-register-reuse
// ============================================================================
template <int STEPS, int NW>
__device__ __forceinline__ void pool_store(
    const float* outs, const float* hs, const float* wa_s,
    float* sc, float* __restrict__ dst)
{
    const int tid  = threadIdx.x;
    const int warp = tid >> 5;
    const int lane = tid & 31;
    constexpr int TL = (STEPS + NW - 1) / NW;

    float acc[TL][2];
#pragma unroll
    for (int tl = 0; tl < TL; tl++) { acc[tl][0] = 0.f; acc[tl][1] = 0.f; }

#pragma unroll 8
    for (int i = 0; i < HH; i++) {
        const float w0 = wa_s[i * HH + lane];
        const float w1 = wa_s[i * HH + 32 + lane];
#pragma unroll
        for (int tl = 0; tl < TL; tl++) {
            const int t = warp + NW * tl;
            if (t < STEPS) {
                const float o = outs[t * HH + i];
                acc[tl][0] = fmaf(o, w0, acc[tl][0]);
                acc[tl][1] = fmaf(o, w1, acc[tl][1]);
            }
        }
    }
#pragma unroll
    for (int tl = 0; tl < TL; tl++) {
        const int t = warp + NW * tl;
        if (t < STEPS) {
            float p = fmaf(ftanh(acc[tl][0]), hs[lane],
                           ftanh(acc[tl][1]) * hs[lane + 32]);
#pragma unroll
            for (int o = 16; o; o >>= 1) p += __shfl_xor_sync(0xffffffffu, p, o);
            if (lane == 0) sc[t] = p;
        }
    }
    __syncthreads();
    if (warp == 0) {
        const float v = (lane < STEPS) ? sc[lane] : -3.4e38f;
        float m = v;
#pragma unroll
        for (int o = 16; o; o >>= 1) m = fmaxf(m, __shfl_xor_sync(0xffffffffu, m, o));
        const float e = (lane < STEPS) ? fexp(v - m) : 0.f;
        float su = e;
#pragma unroll
        for (int o = 16; o; o >>= 1) su += __shfl_xor_sync(0xffffffffu, su, o);
        if (lane < STEPS) sc[lane] = e / su;
    }
    __syncthreads();
    if (tid < HH) {
        float a = 0.f;
#pragma unroll
        for (int t = 0; t < STEPS; t++) a = fmaf(sc[t], outs[t * HH + tid], a);
        dst[tid] = a;
    }
}

// ============================================================================
// Kernel 2a: TENSOR-CORE text GRU recurrence — one block per STOCK, 384 thr.
// ============================================================================
#define HP 25
#define GP 26
#define TCR_THREADS 384
#define TCR_SMEM ((WHS_ELEMS + HH * HP + GG * GP) * 4)

__global__ __launch_bounds__(TCR_THREADS) void k_text_rec_tc(
    const float* __restrict__ Whh, const float* __restrict__ bhh)
{
    extern __shared__ float dyn[];
    float* whs = dyn;                    // staging [192][65]
    float* hsm = whs + WHS_ELEMS;        // h  [64][HP]
    float* ghs = hsm + HH * HP;          // gh [192][GP]

    const int s    = blockIdx.x;
    const int tid  = threadIdx.x;
    const int warp = tid >> 5;           // 0..11
    const int lane = tid & 31;
    const int wm   = warp * 16;

    stage_w(Whh + (size_t)s * GG * HH, whs, tid, TCR_THREADS);
    for (int i = tid; i < HH * HP; i += TCR_THREADS) hsm[i] = 0.f;
    __syncthreads();

    unsigned afr[8][4];
#pragma unroll
    for (int kb = 0; kb < 8; kb++) {
        const int r = wm + (lane >> 2);
        const int c = kb * 8 + (lane & 3);
        afr[kb][0] = __float_as_uint(whs[(r + 0) * WHS_PAD + c + 0]);
        afr[kb][1] = __float_as_uint(whs[(r + 8) * WHS_PAD + c + 0]);
        afr[kb][2] = __float_as_uint(whs[(r + 0) * WHS_PAD + c + 4]);
        afr[kb][3] = __float_as_uint(whs[(r + 8) * WHS_PAD + c + 4]);
    }
    const float bias0 = bhh[s * GG + wm + (lane >> 2)];
    const float bias1 = bhh[s * GG + wm + 8 + (lane >> 2)];

    const __nv_bfloat16* gib = g_gi_bf + (size_t)s * ND * NT * GG;

    float cur0[4], cur1[4], cur2[4];
    float pre0[4], pre1[4], pre2[4];
#pragma unroll
    for (int k = 0; k < 4; k++) {
        const int p = tid + TCR_THREADS * k;
        if (p < ND * HH) {
            const int d = p >> 6, j = p & 63;
            const __nv_bfloat16* gp = gib + ((size_t)d * NT) * GG + j;
            pre0[k] = __bfloat162float(gp[0]);
            pre1[k] = __bfloat162float(gp[64]);
            pre2[k] = __bfloat162float(gp[128]);
        }
    }

    for (int t = 0; t < NT; t++) {
        float acc[3][4];
#pragma unroll
        for (int nt = 0; nt < 3; nt++) {
            acc[nt][0] = bias0; acc[nt][1] = bias0;
            acc[nt][2] = bias1; acc[nt][3] = bias1;
        }
#pragma unroll
        for (int kb = 0; kb < 8; kb++) {
            unsigned bfr[3][2];
            const int k = kb * 8 + (lane & 3);
#pragma unroll
            for (int nt = 0; nt < 3; nt++) {
                const int n = nt * 8 + (lane >> 2);
                bfr[nt][0] = __float_as_uint(hsm[(k + 0) * HP + n]);
                bfr[nt][1] = __float_as_uint(hsm[(k + 4) * HP + n]);
            }
#pragma unroll
            for (int nt = 0; nt < 3; nt++)
                MMA_TF32(acc[nt], afr[kb][0], afr[kb][1], afr[kb][2], afr[kb][3],
                         bfr[nt][0], bfr[nt][1]);
        }
#pragma unroll
        for (int nt = 0; nt < 3; nt++) {
            const int r = wm + (lane >> 2);
            const int d = nt * 8 + (lane & 3) * 2;
            *(float2*)&ghs[(r + 0) * GP + d] = make_float2(acc[nt][0], acc[nt][1]);
            *(float2*)&ghs[(r + 8) * GP + d] = make_float2(acc[nt][2], acc[nt][3]);
        }
        __syncthreads();

#pragma unroll
        for (int k = 0; k < 4; k++) { cur0[k] = pre0[k]; cur1[k] = pre1[k]; cur2[k] = pre2[k]; }
        if (t + 1 < NT) {
#pragma unroll
            for (int k = 0; k < 4; k++) {
                const int p = tid + TCR_THREADS * k;
                if (p < ND * HH) {
                    const int d = p >> 6, j = p & 63;
                    const __nv_bfloat16* gp = gib + ((size_t)d * NT + (t + 1)) * GG + j;
                    pre0[k] = __bfloat162float(gp[0]);
                    pre1[k] = __bfloat162float(gp[64]);
                    pre2[k] = __bfloat162float(gp[128]);
                }
            }
        }

#pragma unroll
        for (int k = 0; k < 4; k++) {
            const int p = tid + TCR_THREADS * k;
            if (p < ND * HH) {
                const int d = p >> 6, j = p & 63;
                const float r  = fsig(cur0[k] + ghs[j * GP + d]);
                const float z  = fsig(cur1[k] + ghs[(64 + j) * GP + d]);
                const float n  = ftanh(cur2[k] + r * ghs[(128 + j) * GP + d]);
                const float hp_ = hsm[j * HP + d];
                const float hn  = (1.f - z) * n + z * hp_;
                hsm[j * HP + d] = hn;
                g_outs[((size_t)(s * ND + d) * NT + t) * HH + j] = hn;
            }
        }
        __syncthreads();
    }
}

// ============================================================================
// Kernel 2b: text attention pooling — one block per (stock, day), 256 threads
// ============================================================================
__global__ __launch_bounds__(256) void k_text_pool(const float* __restrict__ Wa)
{
    __shared__ float outs_s[NT * HH];
    __shared__ float wa_s[HH * HH];
    __shared__ float sc[32];
    const int sd = blockIdx.x;
    const int s  = sd / ND;
    const int g  = threadIdx.x;

    const float4* src = (const float4*)(g_outs + (size_t)sd * NT * HH);
    for (int i = g; i < (NT * HH) / 4; i += 256) ((float4*)outs_s)[i] = src[i];
    const float4* wsrc = (const float4*)(Wa + (size_t)s * HH * HH);
    for (int i = g; i < (HH * HH) / 4; i += 256) ((float4*)wa_s)[i] = wsrc[i];
    __syncthreads();

    pool_store<NT, 8>(outs_s, outs_s + (NT - 1) * HH, wa_s, sc, g_news + (size_t)sd * HH);
}

// ============================================================================
// Kernel 3: generic per-stock GRU + pool; single staging phase (192 threads)
// ============================================================================
template <int IN, int STEPS, int SRC>
__global__ __launch_bounds__(192) void k_gru_pool(
    const float* __restrict__ xin,
    const float* __restrict__ Wih, const float* __restrict__ Whh,
    const float* __restrict__ bih, const float* __restrict__ bhh,
    const float* __restrict__ Wa)
{
    extern __shared__ float dyn[];
    float* whh_s = dyn;
    float* wih_s = whh_s + WHS_ELEMS;
    float* gis   = wih_s + (IN == HH ? WHS_ELEMS : 0);
    float* outs  = gis + STEPS * GG;
    float* wa_s  = outs + STEPS * HH;
    float* xs    = wa_s + HH * HH;
    float* hs    = xs + STEPS * IN;
    float* ghs   = hs + HH;
    float* sc    = ghs + GG;

    const int s = blockIdx.x;
    const int g = threadIdx.x;

    const float* xb = (SRC == 1) ? (g_news + (size_t)s * ND * HH)
                                 : (xin + (size_t)s * STEPS * IN);
    const float bh = bhh[s * GG + g];
    const float bi = bih[s * GG + g];

    for (int i = g; i < STEPS * IN; i += 192) xs[i] = xb[i];
    {
        const float4* src = (const float4*)(Wa + (size_t)s * HH * HH);
        for (int i = g; i < (HH * HH) / 4; i += 192) ((float4*)wa_s)[i] = src[i];
    }
    stage_w(Whh + (size_t)s * GG * HH, whh_s, g, 192);
    if (IN == HH) stage_w(Wih + (size_t)s * GG * IN, wih_s, g, 192);
    float wi[IN <= 4 ? IN : 1];
    if (IN != HH) {
        const float* wip = Wih + ((size_t)s * GG + g) * IN;
#pragma unroll
        for (int i = 0; i < IN; i++) wi[i] = wip[i];
    }
    if (g < HH) hs[g] = 0.f;
    __syncthreads();

    if (IN == HH) {
        float acct[STEPS];
#pragma unroll
        for (int t = 0; t < STEPS; t++) acct[t] = bi;
#pragma unroll 4
        for (int i = 0; i < IN; i++) {
            const float w = wih_s[g * WHS_PAD + i];
#pragma unroll
            for (int t = 0; t < STEPS; t++) acct[t] = fmaf(w, xs[t * IN + i], acct[t]);
        }
#pragma unroll
        for (int t = 0; t < STEPS; t++) gis[t * GG + g] = acct[t];
    } else {
#pragma unroll
        for (int t = 0; t < STEPS; t++) {
            float gi = bi;
#pragma unroll
            for (int i = 0; i < IN; i++) gi = fmaf(wi[i], xs[t * IN + i], gi);
            gis[t * GG + g] = gi;
        }
    }
    __syncthreads();

    float wh[HH];
#pragma unroll
    for (int i = 0; i < HH; i++) wh[i] = whh_s[g * WHS_PAD + i];

    for (int t = 0; t < STEPS; t++) {
        float a0 = 0.f, a1 = 0.f, a2 = 0.f, a3 = 0.f;
#pragma unroll
        for (int i = 0; i < HH; i += 4) {
            a0 = fmaf(wh[i + 0], hs[i + 0], a0);
            a1 = fmaf(wh[i + 1], hs[i + 1], a1);
            a2 = fmaf(wh[i + 2], hs[i + 2], a2);
            a3 = fmaf(wh[i + 3], hs[i + 3], a3);
        }
        ghs[g] = bh + ((a0 + a1) + (a2 + a3));
        __syncthreads();
        if (g < HH) {
            const float* git = gis + t * GG;
            const float r  = fsig(git[g] + ghs[g]);
            const float z  = fsig(git[HH + g] + ghs[HH + g]);
            const float n  = ftanh(git[2 * HH + g] + r * ghs[2 * HH + g]);
            const float hn = (1.f - z) * n + z * hs[g];
            hs[g] = hn;
            outs[t * HH + g] = hn;
        }
        __syncthreads();
    }
    float* dst = (SRC == 1 ? g_tvec : g_pvec) + s * HH;
    pool_store<STEPS, 6>(outs, hs, wa_s, sc, dst);
}

// ============================================================================
// Kernel 4: bilinear fusion
// ============================================================================
__global__ __launch_bounds__(128) void k_bilinear(
    const float* __restrict__ B, const float* __restrict__ bb)
{
    const int o = blockIdx.x, s = blockIdx.y;
    const int tid = threadIdx.x;
    __shared__ float tv_s[HH], pv_s[HH];
    if (tid < HH) { tv_s[tid] = g_tvec[s * HH + tid]; pv_s[tid] = g_pvec[s * HH + tid]; }
    __syncthreads();

    const float* Bp = B + ((size_t)s * HH + o) * HH * HH;
    float acc = 0.f;
#pragma unroll
    for (int it = 0; it < 8; it++) {
        const int k4 = (it * 128 + tid) * 4;
        const float4 v = *(const float4*)(Bp + k4);
        const int i = k4 >> 6, j = k4 & 63;
        float p = pv_s[j] * v.x;
        p = fmaf(pv_s[j + 1], v.y, p);
        p = fmaf(pv_s[j + 2], v.z, p);
        p = fmaf(pv_s[j + 3], v.w, p);
        acc = fmaf(tv_s[i], p, acc);
    }
    __shared__ float red[128];
    red[tid] = acc;
    __syncthreads();
    for (int st2 = 64; st2; st2 >>= 1) {
        if (tid < st2) red[tid] += red[tid + st2];
        __syncthreads();
    }
    if (tid == 0) g_feat[s * HH + o] = ftanh(red[0] + bb[s * HH + o]);
}

// ============================================================================
// Kernel 5: GAT head projection
// ============================================================================
__global__ __launch_bounds__(64) void k_gat_proj(
    const float* __restrict__ gatW, const float* __restrict__ gatA)
{
    const int s = blockIdx.x, nh = blockIdx.y;
    const int j = threadIdx.x;
    const float* Wp = gatW + (size_t)nh * HH * HH;
    const float* x  = g_feat + s * HH;
    float acc = 0.f;
#pragma unroll 8
    for (int i = 0; i < HH; i++) acc = fmaf(x[i], Wp[i * HH + j], acc);
    g_hgat[((size_t)nh * NS + s) * HH + j] = acc;

    __shared__ float r1[64], r2[64];
    r1[j] = acc * gatA[nh * 2 * HH + j];
    r2[j] = acc * gatA[nh * 2 * HH + HH + j];
    __syncthreads();
    if (j < 32) {
        float v1 = r1[j] + r1[j + 32];
        float v2 = r2[j] + r2[j + 32];
#pragma unroll
        for (int o = 16; o; o >>= 1) {
            v1 += __shfl_xor_sync(0xffffffffu, v1, o);
            v2 += __shfl_xor_sync(0xffffffffu, v2, o);
        }
        if (j == 0) { g_f1[nh * NS + s] = v1; g_f2[nh * NS + s] = v2; }
    }
}

// ============================================================================
// Kernel 6: GAT masked attention + elu
// ============================================================================
__global__ __launch_bounds__(128) void k_gat_attn(const float* __restrict__ adj)
{
    const int s = blockIdx.x, nh = blockIdx.y;
    const int tid = threadIdx.x;
    __shared__ float att[NS];
    __shared__ float sinv;
    const float f1v = g_f1[nh * NS + s];
    if (tid < NS) {
        float v = f1v + g_f2[nh * NS + tid];
        v = (v >= 0.f) ? v : 0.2f * v;
        att[tid] = (adj[s * NS + tid] > 0.f) ? v : -9e15f;
    }
    __syncthreads();
    if (tid < 32) {
        float m = -3.4e38f;
        for (int t = tid; t < NS; t += 32) m = fmaxf(m, att[t]);
#pragma unroll
        for (int o = 16; o; o >>= 1) m = fmaxf(m, __shfl_xor_sync(0xffffffffu, m, o));
        float su = 0.f;
        for (int t = tid; t < NS; t += 32) {
            const float e = fexp(att[t] - m);
            att[t] = e;
            su += e;
        }
#pragma unroll
        for (int o = 16; o; o >>= 1) su += __shfl_xor_sync(0xffffffffu, su, o);
        if (tid == 0) sinv = 1.f / su;
    }
    __syncthreads();
    if (tid < HH) {
        float acc = 0.f;
        for (int t = 0; t < NS; t++)
            acc = fmaf(att[t], g_hgat[((size_t)nh * NS + t) * HH + tid], acc);
        acc = felu(acc * sinv);
        g_x2[(size_t)s * (NHD * HH) + nh * HH + tid] = acc;
    }
}

// ============================================================================
// Kernel 7: final — out-layer GAT, blend, double softmax, loss. One block.
// ============================================================================
__global__ __launch_bounds__(128) void k_final(
    const float* __restrict__ blW, const float* __restrict__ blb,
    const float* __restrict__ outW, const float* __restrict__ outA,
    const float* __restrict__ adj, const int* __restrict__ label,
    float* __restrict__ out, int out_size)
{
    __shared__ float h2[NS][2];
    __shared__ float f1s[NS], f2s[NS];
    __shared__ float o1[NS][2];
    __shared__ float adj_s[NS * NS];
    __shared__ float red[128];
    const int tid  = threadIdx.x;
    const int warp = tid >> 5;
    const int lane = tid & 31;

    for (int i = tid; i < NS * NS; i += 128) adj_s[i] = adj[i];

    for (int s = warp; s < NS; s += 4) {
        const float* xr = g_x2 + (size_t)s * NHD * HH;
        float a0 = 0.f, a1 = 0.f;
        for (int k = lane; k < NHD * HH; k += 32) {
            const float xv = xr[k];
            a0 = fmaf(xv, outW[2 * k + 0], a0);
            a1 = fmaf(xv, outW[2 * k + 1], a1);
        }
        const float* fr = g_feat + s * HH;
        float b0 = 0.f, b1 = 0.f;
        for (int k = lane; k < HH; k += 32) {
            const float fv = fr[k];
            b0 = fmaf(fv, blW[2 * k + 0], b0);
            b1 = fmaf(fv, blW[2 * k + 1], b1);
        }
#pragma unroll
        for (int o = 16; o; o >>= 1) {
            a0 += __shfl_xor_sync(0xffffffffu, a0, o);
            a1 += __shfl_xor_sync(0xffffffffu, a1, o);
            b0 += __shfl_xor_sync(0xffffffffu, b0, o);
            b1 += __shfl_xor_sync(0xffffffffu, b1, o);
        }
        if (lane == 0) {
            h2[s][0] = a0; h2[s][1] = a1;
            f1s[s] = a0 * outA[0] + a1 * outA[1];
            f2s[s] = a0 * outA[2] + a1 * outA[3];
            o1[s][0] = ftanh(b0 + blb[0]);
            o1[s][1] = ftanh(b1 + blb[1]);
        }
    }
    __syncthreads();

    const int off = (out_size > 200) ? (out_size - 200) : 0;
    float lsum = 0.f;
    for (int s = tid; s < NS; s += 128) {
        float m = -3.4e38f;
        for (int t = 0; t < NS; t++) {
            float v = f1s[s] + f2s[t];
            v = (v >= 0.f) ? v : 0.2f * v;
            v = (adj_s[s * NS + t] > 0.f) ? v : -9e15f;
            m = fmaxf(m, v);
        }
        float su = 0.f, a0 = 0.f, a1 = 0.f;
        for (int t = 0; t < NS; t++) {
            float v = f1s[s] + f2s[t];
            v = (v >= 0.f) ? v : 0.2f * v;
            v = (adj_s[s * NS + t] > 0.f) ? v : -9e15f;
            const float e = fexp(v - m);
            su += e;
            a0 = fmaf(e, h2[t][0], a0);
            a1 = fmaf(e, h2[t][1], a1);
        }
        a0 /= su; a1 /= su;
        a0 = felu(a0);
        a1 = felu(a1);
        const float z0 = a0 + o1[s][0];
        const float z1 = a1 + o1[s][1];
        const float zm = fmaxf(z0, z1);
        const float e0 = fexp(z0 - zm), e1 = fexp(z1 - zm);
        const float p0 = e0 / (e0 + e1), p1 = e1 / (e0 + e1);
        if (out_size >= 200) { out[off + 2 * s] = p0; out[off + 2 * s + 1] = p1; }
        const float pm  = fmaxf(p0, p1);
        const float lse = pm + logf(fexp(p0 - pm) + fexp(p1 - pm));
        const float chosen = (label[s] == 0) ? p0 : p1;
        lsum += (lse - chosen);
    }
    red[tid] = lsum;
    __syncthreads();
    for (int st2 = 64; st2; st2 >>= 1) {
        if (tid < st2) red[tid] += red[tid + st2];
        __syncthreads();
    }
    if (tid == 0 && (out_size == 1 || out_size > 200)) out[0] = red[0] * (1.f / NS);
}

// ============================================================================
extern "C" void kernel_launch(void* const* d_in, const int* in_sizes, int n_in,
                              void* d_out, int out_size)
{
    (void)in_sizes;
    const float* text  = (const float*)d_in[0];
    const float* price = (const float*)d_in[1];
    const int*   label = (const int*)d_in[2];
    const float* adj   = (const float*)d_in[3];
    const int wb = n_in - 23;
    const float* pg_Wih = (const float*)d_in[wb + 0];
    const float* pg_Whh = (const float*)d_in[wb + 1];
    const float* pg_bih = (const float*)d_in[wb + 2];
    const float* pg_bhh = (const float*)d_in[wb + 3];
    const float* pa_W   = (const float*)d_in[wb + 4];
    const float* tg_Wih = (const float*)d_in[wb + 5];
    const float* tg_Whh = (const float*)d_in[wb + 6];
    const float* tg_bih = (const float*)d_in[wb + 7];
    const float* tg_bhh = (const float*)d_in[wb + 8];
    const float* ta_W   = (const float*)d_in[wb + 9];
    const float* sg_Wih = (const float*)d_in[wb + 10];
    const float* sg_Whh = (const float*)d_in[wb + 11];
    const float* sg_bih = (const float*)d_in[wb + 12];
    const float* sg_bhh = (const float*)d_in[wb + 13];
    const float* sa_W   = (const float*)d_in[wb + 14];
    const float* bil_B  = (const float*)d_in[wb + 15];
    const float* bil_b  = (const float*)d_in[wb + 16];
    const float* bl_W   = (const float*)d_in[wb + 17];
    const float* bl_b   = (const float*)d_in[wb + 18];
    const float* gat_W  = (const float*)d_in[wb + 19];
    const float* gat_a  = (const float*)d_in[wb + 20];
    const float* out_W  = (const float*)d_in[wb + 21];
    const float* out_a  = (const float*)d_in[wb + 22];

    const int smem_gru64 = (2 * WHS_ELEMS + ND * GG + ND * HH + HH * HH + ND * HH + HH + GG + 32) * 4;
    const int smem_gru3  = (WHS_ELEMS + ND * GG + ND * HH + HH * HH + ND * FP + HH + GG + 32) * 4;

    static cudaStream_t s2 = nullptr;
    static cudaEvent_t evA = nullptr, evB = nullptr;
    if (!s2) {
        cudaFuncSetAttribute(k_gemm_tf32,
                             cudaFuncAttributeMaxDynamicSharedMemorySize, GEMM2_SMEM);
        cudaFuncSetAttribute(k_text_rec_tc,
                             cudaFuncAttributeMaxDynamicSharedMemorySize, TCR_SMEM);
        cudaFuncSetAttribute((const void*)k_gru_pool<HH, ND, 1>,
                             cudaFuncAttributeMaxDynamicSharedMemorySize, smem_gru64);
        cudaFuncSetAttribute((const void*)k_gru_pool<FP, ND, 0>,
                             cudaFuncAttributeMaxDynamicSharedMemorySize, smem_gru3);
        cudaStreamCreateWithFlags(&s2, cudaStreamNonBlocking);
        cudaEventCreateWithFlags(&evA, cudaEventDisableTiming);
        cudaEventCreateWithFlags(&evB, cudaEventDisableTiming);
    }

    // fork: price path runs concurrently with the text path
    cudaEventRecord(evA, 0);
    cudaStreamWaitEvent(s2, evA, 0);
    k_gru_pool<FP, ND, 0><<<NS, 192, smem_gru3, s2>>>(price, pg_Wih, pg_Whh, pg_bih, pg_bhh, pa_W);
    cudaEventRecord(evB, s2);

    // text path (main stream)
    k_gemm_tf32<<<dim3(10, NS), 256, GEMM2_SMEM>>>(text, tg_Wih, tg_bih);
    k_text_rec_tc<<<NS, TCR_THREADS, TCR_SMEM>>>(tg_Whh, tg_bhh);
    k_text_pool<<<NS * ND, 256>>>(ta_W);
    k_gru_pool<HH, ND, 1><<<NS, 192, smem_gru64>>>(nullptr, sg_Wih, sg_Whh, sg_bih, sg_bhh, sa_W);

    // join price path, then fusion + GAT + output
    cudaStreamWaitEvent(0, evB, 0);
    k_bilinear<<<dim3(HH, NS), 128>>>(bil_B, bil_b);
    k_gat_proj<<<dim3(NS, NHD), 64>>>(gat_W, gat_a);
    k_gat_attn<<<dim3(NS, NHD), 128>>>(adj);
    k_final<<<1, 128>>>(bl_W, bl_b, out_W, out_a, adj, label, (float*)d_out, out_size);
}

// round 17
// speedup vs baseline: 1.0159x; 1.0094x over previous
#include <cuda_runtime.h>
#include <cuda_bf16.h>
#include <math.h>

#define NS 100     // stocks
#define ND 20      // days
#define NT 30      // texts per day
#define HH 64      // hidden
#define GG 192     // 3*H
#define NHD 8      // GAT heads
#define FT 512     // text feature
#define FP 3       // price feature
#define MROWS 600  // ND*NT

#define WHS_PAD 65
#define WHS_ELEMS (GG * WHS_PAD)   // 12480 floats

// ---------------- scratch (device globals; no runtime allocation) ----------------
__device__ __nv_bfloat16 g_gi_bf[(size_t)NS * MROWS * GG];  // text GRU input projections (bf16)
__device__ float g_outs[(size_t)NS * ND * NT * HH];         // text GRU hidden states
__device__ float g_news[NS * ND * HH];
__device__ float g_pvec[NS * HH];
__device__ float g_tvec[NS * HH];
__device__ float g_feat[NS * HH];
__device__ float g_hgat[NHD * NS * HH];
__device__ float g_f1[NHD * NS];
__device__ float g_f2[NHD * NS];
__device__ float g_x2[NS * NHD * HH];

#define LOG2E 1.4426950408889634f

__device__ __forceinline__ float fexp2(float x) { float r; asm("ex2.approx.f32 %0,%1;" : "=f"(r) : "f"(x)); return r; }
__device__ __forceinline__ float frcp(float x)  { float r; asm("rcp.approx.f32 %0,%1;" : "=f"(r) : "f"(x)); return r; }
__device__ __forceinline__ float ftanh(float x) { float r; asm("tanh.approx.f32 %0,%1;" : "=f"(r) : "f"(x)); return r; }
__device__ __forceinline__ float fsig(float x)  { return fmaf(0.5f, ftanh(0.5f * x), 0.5f); }
__device__ __forceinline__ float fexp(float x)  { return fexp2(LOG2E * x); }
__device__ __forceinline__ float felu(float x)  { return (x > 0.f) ? x : (fexp(x) - 1.f); }

__device__ __forceinline__ unsigned smem_u32(const void* p) {
    return (unsigned)__cvta_generic_to_shared(p);
}

// coalesced stage of a [192,64] fp32 matrix into padded smem [192][65]
__device__ __forceinline__ void stage_w(const float* __restrict__ src, float* whs, int tid, int nthr)
{
    const float4* s4 = (const float4*)src;
    for (int idx = tid; idx < (GG * HH) / 4; idx += nthr) {
        const float4 v = s4[idx];
        const int base = idx * 4;
        const int row = base >> 6;
        const int col = base & 63;
        float* d = whs + row * WHS_PAD + col;
        d[0] = v.x; d[1] = v.y; d[2] = v.z; d[3] = v.w;
    }
}

#define MMA_TF32(c, a0, a1, a2, a3, b0, b1) \
    asm volatile("mma.sync.aligned.m16n8k8.row.col.f32.tf32.tf32.f32 " \
                 "{%0,%1,%2,%3},{%4,%5,%6,%7},{%8,%9},{%0,%1,%2,%3};" \
                 : "+f"((c)[0]), "+f"((c)[1]), "+f"((c)[2]), "+f"((c)[3]) \
                 : "r"(a0), "r"(a1), "r"(a2), "r"(a3), "r"(b0), "r"(b1))

#define LDSM4(r0, r1, r2, r3, addr) \
    asm volatile("ldmatrix.sync.aligned.m8n8.x4.shared.b16 {%0,%1,%2,%3},[%4];" \
                 : "=r"(r0), "=r"(r1), "=r"(r2), "=r"(r3) : "r"(addr))

// ============================================================================
// Kernel 1: tf32 tensor-core GEMM, 2-stage cp.async, occ 3, single launch,
//           ldmatrix fragment loads.
// ============================================================================
#define GBM 64
#define GBK 32
#define GPAD 36
#define GA_STAGE (GBM * GPAD)
#define GB_STAGE (GG * GPAD)
#define GSTAGE (GA_STAGE + GB_STAGE)
#define GEMM2_SMEM (GSTAGE * 2 * 4)

#define CPA16(dst, src, pred) do {                                          \
    unsigned _ds = smem_u32(dst);                                           \
    int _sz = (pred) ? 16 : 0;                                              \
    asm volatile("cp.async.cg.shared.global [%0],[%1],16,%2;"               \
                 :: "r"(_ds), "l"(src), "r"(_sz));                          \
} while (0)
#define CPA_COMMIT() asm volatile("cp.async.commit_group;")
#define CPA_WAIT(n)  asm volatile("cp.async.wait_group %0;" :: "n"(n))

__global__ __launch_bounds__(256, 3) void k_gemm_tf32(
    const float* __restrict__ A, const float* __restrict__ W,
    const float* __restrict__ bih)
{
    extern __shared__ float smf[];
    const int s  = blockIdx.y;
    const int m0 = blockIdx.x * GBM;

    const float* Ab = A + (size_t)s * MROWS * FT;
    const float* Wb = W + (size_t)s * GG * FT;

    const int tid  = threadIdx.x;
    const int lane = tid & 31;
    const int warp = tid >> 5;
    const int wm   = (warp & 1) * 32;
    const int wn   = (warp >> 1) * 48;

    const int lmoff = ((lane & 7) + ((lane >> 3) & 1) * 8) * GPAD + ((lane >> 4) << 2);

    float acc[2][6][4];
#pragma unroll
    for (int mi = 0; mi < 2; mi++)
#pragma unroll
        for (int j = 0; j < 6; j++)
#pragma unroll
            for (int v = 0; v < 4; v++) acc[mi][j][v] = 0.f;

    const int lr = tid >> 3;
    const int lc = (tid & 7) * 4;

    auto load_tile = [&](int kt, int stage) {
        const int k0 = kt * GBK;
        float* base = smf + stage * GSTAGE;
#pragma unroll
        for (int i = 0; i < 2; i++) {
            const int r = lr + 32 * i;
            const float* src = Ab + (size_t)(m0 + r) * FT + k0 + lc;
            CPA16(base + r * GPAD + lc, src, (m0 + r) < MROWS);
        }
#pragma unroll
        for (int i = 0; i < 6; i++) {
            const int r = lr + 32 * i;
            const float* src = Wb + (size_t)r * FT + k0 + lc;
            CPA16(base + GA_STAGE + r * GPAD + lc, src, true);
        }
        CPA_COMMIT();
    };

    const int NKT = FT / GBK;   // 16
    load_tile(0, 0);
    CPA_WAIT(0);
    __syncthreads();

    for (int kt = 0; kt < NKT; kt++) {
        const int cur = kt & 1;
        if (kt + 1 < NKT) load_tile(kt + 1, cur ^ 1);

        const float* As_ = smf + cur * GSTAGE;
        const float* Bs_ = As_ + GA_STAGE;
        const unsigned abase = smem_u32(As_) + ((wm * GPAD) + lmoff) * 4;
        const unsigned bbase = smem_u32(Bs_) + ((wn * GPAD) + lmoff) * 4;

#pragma unroll
        for (int ks = 0; ks < 4; ks++) {
            const int kb = ks * 8;
            unsigned a[2][4];
#pragma unroll
            for (int mi = 0; mi < 2; mi++) {
                const unsigned addr = abase + (mi * 16 * GPAD + kb) * 4;
                LDSM4(a[mi][0], a[mi][1], a[mi][2], a[mi][3], addr);
            }
            unsigned b[6][2];
#pragma unroll
            for (int nj = 0; nj < 3; nj++) {
                const unsigned addr = bbase + (nj * 16 * GPAD + kb) * 4;
                unsigned t0, t1, t2, t3;
                LDSM4(t0, t1, t2, t3, addr);
                b[2 * nj][0] = t0; b[2 * nj + 1][0] = t1;
                b[2 * nj][1] = t2; b[2 * nj + 1][1] = t3;
            }
#pragma unroll
            for (int mi = 0; mi < 2; mi++)
#pragma unroll
                for (int j = 0; j < 6; j++)
                    MMA_TF32(acc[mi][j], a[mi][0], a[mi][1], a[mi][2], a[mi][3],
                             b[j][0], b[j][1]);
        }
        __syncthreads();
        if (kt + 1 < NKT) {
            CPA_WAIT(0);
            __syncthreads();
        }
    }

#pragma unroll
    for (int mi = 0; mi < 2; mi++) {
        const int row0 = m0 + wm + mi * 16 + (lane >> 2);
#pragma unroll
        for (int j = 0; j < 6; j++) {
            const int col = wn + j * 8 + (lane & 3) * 2;
            const float b0 = bih[s * GG + col];
            const float b1 = bih[s * GG + col + 1];
            if (row0 < MROWS) {
                __nv_bfloat162 v = __float22bfloat162_rn(
                    make_float2(acc[mi][j][0] + b0, acc[mi][j][1] + b1));
                *(__nv_bfloat162*)(g_gi_bf + ((size_t)s * MROWS + row0) * GG + col) = v;
            }
            if (row0 + 8 < MROWS) {
                __nv_bfloat162 v = __float22bfloat162_rn(
                    make_float2(acc[mi][j][2] + b0, acc[mi][j][3] + b1));
                *(__nv_bfloat162*)(g_gi_bf + ((size_t)s * MROWS + row0 + 8) * GG + col) = v;
            }
        }
    }
}

// ============================================================================
// Attention pool, warp-count templated (NW warps): Wa-register-reuse +
// float4-broadcast outs loads (4x fewer outs LDS wavefronts).
// ============================================================================
template <int STEPS, int NW>
__device__ __forceinline__ void pool_store(
    const float* outs, const float* hs, const float* wa_s,
    float* sc, float* __restrict__ dst)
{
    const int tid  = threadIdx.x;
    const int warp = tid >> 5;
    const int lane = tid & 31;
    constexpr int TL = (STEPS + NW - 1) / NW;

    float acc[TL][2];
#pragma unroll
    for (int tl = 0; tl < TL; tl++) { acc[tl][0] = 0.f; acc[tl][1] = 0.f; }

#pragma unroll 4
    for (int i4 = 0; i4 < HH; i4 += 4) {
        float w0[4], w1[4];
#pragma unroll
        for (int u = 0; u < 4; u++) {
            w0[u] = wa_s[(i4 + u) * HH + lane];
            w1[u] = wa_s[(i4 + u) * HH + 32 + lane];
        }
#pragma unroll
        for (int tl = 0; tl < TL; tl++) {
            const int t = warp + NW * tl;
            if (t < STEPS) {
                const float4 o4 = *(const float4*)&outs[t * HH + i4];
                acc[tl][0] = fmaf(o4.x, w0[0], acc[tl][0]);
                acc[tl][1] = fmaf(o4.x, w1[0], acc[tl][1]);
                acc[tl][0] = fmaf(o4.y, w0[1], acc[tl][0]);
                acc[tl][1] = fmaf(o4.y, w1[1], acc[tl][1]);
                acc[tl][0] = fmaf(o4.z, w0[2], acc[tl][0]);
                acc[tl][1] = fmaf(o4.z, w1[2], acc[tl][1]);
                acc[tl][0] = fmaf(o4.w, w0[3], acc[tl][0]);
                acc[tl][1] = fmaf(o4.w, w1[3], acc[tl][1]);
            }
        }
    }
#pragma unroll
    for (int tl = 0; tl < TL; tl++) {
        const int t = warp + NW * tl;
        if (t < STEPS) {
            float p = fmaf(ftanh(acc[tl][0]), hs[lane],
                           ftanh(acc[tl][1]) * hs[lane + 32]);
#pragma unroll
            for (int o = 16; o; o >>= 1) p += __shfl_xor_sync(0xffffffffu, p, o);
            if (lane == 0) sc[t] = p;
        }
    }
    __syncthreads();
    if (warp == 0) {
        const float v = (lane < STEPS) ? sc[lane] : -3.4e38f;
        float m = v;
#pragma unroll
        for (int o = 16; o; o >>= 1) m = fmaxf(m, __shfl_xor_sync(0xffffffffu, m, o));
        const float e = (lane < STEPS) ? fexp(v - m) : 0.f;
        float su = e;
#pragma unroll
        for (int o = 16; o; o >>= 1) su += __shfl_xor_sync(0xffffffffu, su, o);
        if (lane < STEPS) sc[lane] = e / su;
    }
    __syncthreads();
    if (tid < HH) {
        float a = 0.f;
#pragma unroll
        for (int t = 0; t < STEPS; t++) a = fmaf(sc[t], outs[t * HH + tid], a);
        dst[tid] = a;
    }
}

// ============================================================================
// Kernel 2a: TENSOR-CORE text GRU recurrence — one block per STOCK, 384 thr.
// ============================================================================
#define HP 25
#define GP 26
#define TCR_THREADS 384
#define TCR_SMEM ((WHS_ELEMS + HH * HP + GG * GP) * 4)

__global__ __launch_bounds__(TCR_THREADS) void k_text_rec_tc(
    const float* __restrict__ Whh, const float* __restrict__ bhh)
{
    extern __shared__ float dyn[];
    float* whs = dyn;                    // staging [192][65]
    float* hsm = whs + WHS_ELEMS;        // h  [64][HP]
    float* ghs = hsm + HH * HP;          // gh [192][GP]

    const int s    = blockIdx.x;
    const int tid  = threadIdx.x;
    const int warp = tid >> 5;           // 0..11
    const int lane = tid & 31;
    const int wm   = warp * 16;

    stage_w(Whh + (size_t)s * GG * HH, whs, tid, TCR_THREADS);
    for (int i = tid; i < HH * HP; i += TCR_THREADS) hsm[i] = 0.f;
    __syncthreads();

    unsigned afr[8][4];
#pragma unroll
    for (int kb = 0; kb < 8; kb++) {
        const int r = wm + (lane >> 2);
        const int c = kb * 8 + (lane & 3);
        afr[kb][0] = __float_as_uint(whs[(r + 0) * WHS_PAD + c + 0]);
        afr[kb][1] = __float_as_uint(whs[(r + 8) * WHS_PAD + c + 0]);
        afr[kb][2] = __float_as_uint(whs[(r + 0) * WHS_PAD + c + 4]);
        afr[kb][3] = __float_as_uint(whs[(r + 8) * WHS_PAD + c + 4]);
    }
    const float bias0 = bhh[s * GG + wm + (lane >> 2)];
    const float bias1 = bhh[s * GG + wm + 8 + (lane >> 2)];

    const __nv_bfloat16* gib = g_gi_bf + (size_t)s * ND * NT * GG;

    float cur0[4], cur1[4], cur2[4];
    float pre0[4], pre1[4], pre2[4];
#pragma unroll
    for (int k = 0; k < 4; k++) {
        const int p = tid + TCR_THREADS * k;
        if (p < ND * HH) {
            const int d = p >> 6, j = p & 63;
            const __nv_bfloat16* gp = gib + ((size_t)d * NT) * GG + j;
            pre0[k] = __bfloat162float(gp[0]);
            pre1[k] = __bfloat162float(gp[64]);
            pre2[k] = __bfloat162float(gp[128]);
        }
    }

    for (int t = 0; t < NT; t++) {
        float acc[3][4];
#pragma unroll
        for (int nt = 0; nt < 3; nt++) {
            acc[nt][0] = bias0; acc[nt][1] = bias0;
            acc[nt][2] = bias1; acc[nt][3] = bias1;
        }
#pragma unroll
        for (int kb = 0; kb < 8; kb++) {
            unsigned bfr[3][2];
            const int k = kb * 8 + (lane & 3);
#pragma unroll
            for (int nt = 0; nt < 3; nt++) {
                const int n = nt * 8 + (lane >> 2);
                bfr[nt][0] = __float_as_uint(hsm[(k + 0) * HP + n]);
                bfr[nt][1] = __float_as_uint(hsm[(k + 4) * HP + n]);
            }
#pragma unroll
            for (int nt = 0; nt < 3; nt++)
                MMA_TF32(acc[nt], afr[kb][0], afr[kb][1], afr[kb][2], afr[kb][3],
                         bfr[nt][0], bfr[nt][1]);
        }
#pragma unroll
        for (int nt = 0; nt < 3; nt++) {
            const int r = wm + (lane >> 2);
            const int d = nt * 8 + (lane & 3) * 2;
            *(float2*)&ghs[(r + 0) * GP + d] = make_float2(acc[nt][0], acc[nt][1]);
            *(float2*)&ghs[(r + 8) * GP + d] = make_float2(acc[nt][2], acc[nt][3]);
        }
        __syncthreads();

#pragma unroll
        for (int k = 0; k < 4; k++) { cur0[k] = pre0[k]; cur1[k] = pre1[k]; cur2[k] = pre2[k]; }
        if (t + 1 < NT) {
#pragma unroll
            for (int k = 0; k < 4; k++) {
                const int p = tid + TCR_THREADS * k;
                if (p < ND * HH) {
                    const int d = p >> 6, j = p & 63;
                    const __nv_bfloat16* gp = gib + ((size_t)d * NT + (t + 1)) * GG + j;
                    pre0[k] = __bfloat162float(gp[0]);
                    pre1[k] = __bfloat162float(gp[64]);
                    pre2[k] = __bfloat162float(gp[128]);
                }
            }
        }

#pragma unroll
        for (int k = 0; k < 4; k++) {
            const int p = tid + TCR_THREADS * k;
            if (p < ND * HH) {
                const int d = p >> 6, j = p & 63;
                const float r  = fsig(cur0[k] + ghs[j * GP + d]);
                const float z  = fsig(cur1[k] + ghs[(64 + j) * GP + d]);
                const float n  = ftanh(cur2[k] + r * ghs[(128 + j) * GP + d]);
                const float hp_ = hsm[j * HP + d];
                const float hn  = (1.f - z) * n + z * hp_;
                hsm[j * HP + d] = hn;
                g_outs[((size_t)(s * ND + d) * NT + t) * HH + j] = hn;
            }
        }
        __syncthreads();
    }
}

// ============================================================================
// Kernel 2b: text attention pooling — one block per (stock, day), 256 threads
// ============================================================================
__global__ __launch_bounds__(256) void k_text_pool(const float* __restrict__ Wa)
{
    __shared__ float outs_s[NT * HH];
    __shared__ float wa_s[HH * HH];
    __shared__ float sc[32];
    const int sd = blockIdx.x;
    const int s  = sd / ND;
    const int g  = threadIdx.x;

    const float4* src = (const float4*)(g_outs + (size_t)sd * NT * HH);
    for (int i = g; i < (NT * HH) / 4; i += 256) ((float4*)outs_s)[i] = src[i];
    const float4* wsrc = (const float4*)(Wa + (size_t)s * HH * HH);
    for (int i = g; i < (HH * HH) / 4; i += 256) ((float4*)wa_s)[i] = wsrc[i];
    __syncthreads();

    pool_store<NT, 8>(outs_s, outs_s + (NT - 1) * HH, wa_s, sc, g_news + (size_t)sd * HH);
}

// ============================================================================
// Kernel 3: generic per-stock GRU + pool; single staging phase (192 threads)
// ============================================================================
template <int IN, int STEPS, int SRC>
__global__ __launch_bounds__(192) void k_gru_pool(
    const float* __restrict__ xin,
    const float* __restrict__ Wih, const float* __restrict__ Whh,
    const float* __restrict__ bih, const float* __restrict__ bhh,
    const float* __restrict__ Wa)
{
    extern __shared__ float dyn[];
    float* whh_s = dyn;
    float* wih_s = whh_s + WHS_ELEMS;
    float* gis   = wih_s + (IN == HH ? WHS_ELEMS : 0);
    float* outs  = gis + STEPS * GG;
    float* wa_s  = outs + STEPS * HH;
    float* xs    = wa_s + HH * HH;
    float* hs    = xs + STEPS * IN;
    float* ghs   = hs + HH;
    float* sc    = ghs + GG;

    const int s = blockIdx.x;
    const int g = threadIdx.x;

    const float* xb = (SRC == 1) ? (g_news + (size_t)s * ND * HH)
                                 : (xin + (size_t)s * STEPS * IN);
    const float bh = bhh[s * GG + g];
    const float bi = bih[s * GG + g];

    for (int i = g; i < STEPS * IN; i += 192) xs[i] = xb[i];
    {
        const float4* src = (const float4*)(Wa + (size_t)s * HH * HH);
        for (int i = g; i < (HH * HH) / 4; i += 192) ((float4*)wa_s)[i] = src[i];
    }
    stage_w(Whh + (size_t)s * GG * HH, whh_s, g, 192);
    if (IN == HH) stage_w(Wih + (size_t)s * GG * IN, wih_s, g, 192);
    float wi[IN <= 4 ? IN : 1];
    if (IN != HH) {
        const float* wip = Wih + ((size_t)s * GG + g) * IN;
#pragma unroll
        for (int i = 0; i < IN; i++) wi[i] = wip[i];
    }
    if (g < HH) hs[g] = 0.f;
    __syncthreads();

    if (IN == HH) {
        float acct[STEPS];
#pragma unroll
        for (int t = 0; t < STEPS; t++) acct[t] = bi;
#pragma unroll 4
        for (int i = 0; i < IN; i++) {
            const float w = wih_s[g * WHS_PAD + i];
#pragma unroll
            for (int t = 0; t < STEPS; t++) acct[t] = fmaf(w, xs[t * IN + i], acct[t]);
        }
#pragma unroll
        for (int t = 0; t < STEPS; t++) gis[t * GG + g] = acct[t];
    } else {
#pragma unroll
        for (int t = 0; t < STEPS; t++) {
            float gi = bi;
#pragma unroll
            for (int i = 0; i < IN; i++) gi = fmaf(wi[i], xs[t * IN + i], gi);
            gis[t * GG + g] = gi;
        }
    }
    __syncthreads();

    float wh[HH];
#pragma unroll
    for (int i = 0; i < HH; i++) wh[i] = whh_s[g * WHS_PAD + i];

    for (int t = 0; t < STEPS; t++) {
        float a0 = 0.f, a1 = 0.f, a2 = 0.f, a3 = 0.f;
#pragma unroll
        for (int i = 0; i < HH; i += 4) {
            a0 = fmaf(wh[i + 0], hs[i + 0], a0);
            a1 = fmaf(wh[i + 1], hs[i + 1], a1);
            a2 = fmaf(wh[i + 2], hs[i + 2], a2);
            a3 = fmaf(wh[i + 3], hs[i + 3], a3);
        }
        ghs[g] = bh + ((a0 + a1) + (a2 + a3));
        __syncthreads();
        if (g < HH) {
            const float* git = gis + t * GG;
            const float r  = fsig(git[g] + ghs[g]);
            const float z  = fsig(git[HH + g] + ghs[HH + g]);
            const float n  = ftanh(git[2 * HH + g] + r * ghs[2 * HH + g]);
            const float hn = (1.f - z) * n + z * hs[g];
            hs[g] = hn;
            outs[t * HH + g] = hn;
        }
        __syncthreads();
    }
    float* dst = (SRC == 1 ? g_tvec : g_pvec) + s * HH;
    pool_store<STEPS, 6>(outs, hs, wa_s, sc, dst);
}

// ============================================================================
// Kernel 4: bilinear fusion
// ============================================================================
__global__ __launch_bounds__(128) void k_bilinear(
    const float* __restrict__ B, const float* __restrict__ bb)
{
    const int o = blockIdx.x, s = blockIdx.y;
    const int tid = threadIdx.x;
    __shared__ float tv_s[HH], pv_s[HH];
    if (tid < HH) { tv_s[tid] = g_tvec[s * HH + tid]; pv_s[tid] = g_pvec[s * HH + tid]; }
    __syncthreads();

    const float* Bp = B + ((size_t)s * HH + o) * HH * HH;
    float acc = 0.f;
#pragma unroll
    for (int it = 0; it < 8; it++) {
        const int k4 = (it * 128 + tid) * 4;
        const float4 v = *(const float4*)(Bp + k4);
        const int i = k4 >> 6, j = k4 & 63;
        float p = pv_s[j] * v.x;
        p = fmaf(pv_s[j + 1], v.y, p);
        p = fmaf(pv_s[j + 2], v.z, p);
        p = fmaf(pv_s[j + 3], v.w, p);
        acc = fmaf(tv_s[i], p, acc);
    }
    __shared__ float red[128];
    red[tid] = acc;
    __syncthreads();
    for (int st2 = 64; st2; st2 >>= 1) {
        if (tid < st2) red[tid] += red[tid + st2];
        __syncthreads();
    }
    if (tid == 0) g_feat[s * HH + o] = ftanh(red[0] + bb[s * HH + o]);
}

// ============================================================================
// Kernel 5: GAT head projection
// ============================================================================
__global__ __launch_bounds__(64) void k_gat_proj(
    const float* __restrict__ gatW, const float* __restrict__ gatA)
{
    const int s = blockIdx.x, nh = blockIdx.y;
    const int j = threadIdx.x;
    const float* Wp = gatW + (size_t)nh * HH * HH;
    const float* x  = g_feat + s * HH;
    float acc = 0.f;
#pragma unroll 8
    for (int i = 0; i < HH; i++) acc = fmaf(x[i], Wp[i * HH + j], acc);
    g_hgat[((size_t)nh * NS + s) * HH + j] = acc;

    __shared__ float r1[64], r2[64];
    r1[j] = acc * gatA[nh * 2 * HH + j];
    r2[j] = acc * gatA[nh * 2 * HH + HH + j];
    __syncthreads();
    if (j < 32) {
        float v1 = r1[j] + r1[j + 32];
        float v2 = r2[j] + r2[j + 32];
#pragma unroll
        for (int o = 16; o; o >>= 1) {
            v1 += __shfl_xor_sync(0xffffffffu, v1, o);
            v2 += __shfl_xor_sync(0xffffffffu, v2, o);
        }
        if (j == 0) { g_f1[nh * NS + s] = v1; g_f2[nh * NS + s] = v2; }
    }
}

// ============================================================================
// Kernel 6: GAT masked attention + elu
// ============================================================================
__global__ __launch_bounds__(128) void k_gat_attn(const float* __restrict__ adj)
{
    const int s = blockIdx.x, nh = blockIdx.y;
    const int tid = threadIdx.x;
    __shared__ float att[NS];
    __shared__ float sinv;
    const float f1v = g_f1[nh * NS + s];
    if (tid < NS) {
        float v = f1v + g_f2[nh * NS + tid];
        v = (v >= 0.f) ? v : 0.2f * v;
        att[tid] = (adj[s * NS + tid] > 0.f) ? v : -9e15f;
    }
    __syncthreads();
    if (tid < 32) {
        float m = -3.4e38f;
        for (int t = tid; t < NS; t += 32) m = fmaxf(m, att[t]);
#pragma unroll
        for (int o = 16; o; o >>= 1) m = fmaxf(m, __shfl_xor_sync(0xffffffffu, m, o));
        float su = 0.f;
        for (int t = tid; t < NS; t += 32) {
            const float e = fexp(att[t] - m);
            att[t] = e;
            su += e;
        }
#pragma unroll
        for (int o = 16; o; o >>= 1) su += __shfl_xor_sync(0xffffffffu, su, o);
        if (tid == 0) sinv = 1.f / su;
    }
    __syncthreads();
    if (tid < HH) {
        float acc = 0.f;
        for (int t = 0; t < NS; t++)
            acc = fmaf(att[t], g_hgat[((size_t)nh * NS + t) * HH + tid], acc);
        acc = felu(acc * sinv);
        g_x2[(size_t)s * (NHD * HH) + nh * HH + tid] = acc;
    }
}

// ============================================================================
// Kernel 7: final — out-layer GAT, blend, double softmax, loss. One block.
// ============================================================================
__global__ __launch_bounds__(128) void k_final(
    const float* __restrict__ blW, const float* __restrict__ blb,
    const float* __restrict__ outW, const float* __restrict__ outA,
    const float* __restrict__ adj, const int* __restrict__ label,
    float* __restrict__ out, int out_size)
{
    __shared__ float h2[NS][2];
    __shared__ float f1s[NS], f2s[NS];
    __shared__ float o1[NS][2];
    __shared__ float adj_s[NS * NS];
    __shared__ float red[128];
    const int tid  = threadIdx.x;
    const int warp = tid >> 5;
    const int lane = tid & 31;

    for (int i = tid; i < NS * NS; i += 128) adj_s[i] = adj[i];

    for (int s = warp; s < NS; s += 4) {
        const float* xr = g_x2 + (size_t)s * NHD * HH;
        float a0 = 0.f, a1 = 0.f;
        for (int k = lane; k < NHD * HH; k += 32) {
            const float xv = xr[k];
            a0 = fmaf(xv, outW[2 * k + 0], a0);
            a1 = fmaf(xv, outW[2 * k + 1], a1);
        }
        const float* fr = g_feat + s * HH;
        float b0 = 0.f, b1 = 0.f;
        for (int k = lane; k < HH; k += 32) {
            const float fv = fr[k];
            b0 = fmaf(fv, blW[2 * k + 0], b0);
            b1 = fmaf(fv, blW[2 * k + 1], b1);
        }
#pragma unroll
        for (int o = 16; o; o >>= 1) {
            a0 += __shfl_xor_sync(0xffffffffu, a0, o);
            a1 += __shfl_xor_sync(0xffffffffu, a1, o);
            b0 += __shfl_xor_sync(0xffffffffu, b0, o);
            b1 += __shfl_xor_sync(0xffffffffu, b1, o);
        }
        if (lane == 0) {
            h2[s][0] = a0; h2[s][1] = a1;
            f1s[s] = a0 * outA[0] + a1 * outA[1];
            f2s[s] = a0 * outA[2] + a1 * outA[3];
            o1[s][0] = ftanh(b0 + blb[0]);
            o1[s][1] = ftanh(b1 + blb[1]);
        }
    }
    __syncthreads();

    const int off = (out_size > 200) ? (out_size - 200) : 0;
    float lsum = 0.f;
    for (int s = tid; s < NS; s += 128) {
        float m = -3.4e38f;
        for (int t = 0; t < NS; t++) {
            float v = f1s[s] + f2s[t];
            v = (v >= 0.f) ? v : 0.2f * v;
            v = (adj_s[s * NS + t] > 0.f) ? v : -9e15f;
            m = fmaxf(m, v);
        }
        float su = 0.f, a0 = 0.f, a1 = 0.f;
        for (int t = 0; t < NS; t++) {
            float v = f1s[s] + f2s[t];
            v = (v >= 0.f) ? v : 0.2f * v;
            v = (adj_s[s * NS + t] > 0.f) ? v : -9e15f;
            const float e = fexp(v - m);
            su += e;
            a0 = fmaf(e, h2[t][0], a0);
            a1 = fmaf(e, h2[t][1], a1);
        }
        a0 /= su; a1 /= su;
        a0 = felu(a0);
        a1 = felu(a1);
        const float z0 = a0 + o1[s][0];
        const float z1 = a1 + o1[s][1];
        const float zm = fmaxf(z0, z1);
        const float e0 = fexp(z0 - zm), e1 = fexp(z1 - zm);
        const float p0 = e0 / (e0 + e1), p1 = e1 / (e0 + e1);
        if (out_size >= 200) { out[off + 2 * s] = p0; out[off + 2 * s + 1] = p1; }
        const float pm  = fmaxf(p0, p1);
        const float lse = pm + logf(fexp(p0 - pm) + fexp(p1 - pm));
        const float chosen = (label[s] == 0) ? p0 : p1;
        lsum += (lse - chosen);
    }
    red[tid] = lsum;
    __syncthreads();
    for (int st2 = 64; st2; st2 >>= 1) {
        if (tid < st2) red[tid] += red[tid + st2];
        __syncthreads();
    }
    if (tid == 0 && (out_size == 1 || out_size > 200)) out[0] = red[0] * (1.f / NS);
}

// ============================================================================
extern "C" void kernel_launch(void* const* d_in, const int* in_sizes, int n_in,
                              void* d_out, int out_size)
{
    (void)in_sizes;
    const float* text  = (const float*)d_in[0];
    const float* price = (const float*)d_in[1];
    const int*   label = (const int*)d_in[2];
    const float* adj   = (const float*)d_in[3];
    const int wb = n_in - 23;
    const float* pg_Wih = (const float*)d_in[wb + 0];
    const float* pg_Whh = (const float*)d_in[wb + 1];
    const float* pg_bih = (const float*)d_in[wb + 2];
    const float* pg_bhh = (const float*)d_in[wb + 3];
    const float* pa_W   = (const float*)d_in[wb + 4];
    const float* tg_Wih = (const float*)d_in[wb + 5];
    const float* tg_Whh = (const float*)d_in[wb + 6];
    const float* tg_bih = (const float*)d_in[wb + 7];
    const float* tg_bhh = (const float*)d_in[wb + 8];
    const float* ta_W   = (const float*)d_in[wb + 9];
    const float* sg_Wih = (const float*)d_in[wb + 10];
    const float* sg_Whh = (const float*)d_in[wb + 11];
    const float* sg_bih = (const float*)d_in[wb + 12];
    const float* sg_bhh = (const float*)d_in[wb + 13];
    const float* sa_W   = (const float*)d_in[wb + 14];
    const float* bil_B  = (const float*)d_in[wb + 15];
    const float* bil_b  = (const float*)d_in[wb + 16];
    const float* bl_W   = (const float*)d_in[wb + 17];
    const float* bl_b   = (const float*)d_in[wb + 18];
    const float* gat_W  = (const float*)d_in[wb + 19];
    const float* gat_a  = (const float*)d_in[wb + 20];
    const float* out_W  = (const float*)d_in[wb + 21];
    const float* out_a  = (const float*)d_in[wb + 22];

    const int smem_gru64 = (2 * WHS_ELEMS + ND * GG + ND * HH + HH * HH + ND * HH + HH + GG + 32) * 4;
    const int smem_gru3  = (WHS_ELEMS + ND * GG + ND * HH + HH * HH + ND * FP + HH + GG + 32) * 4;

    static bool init_done = false;
    if (!init_done) {
        cudaFuncSetAttribute(k_gemm_tf32,
                             cudaFuncAttributeMaxDynamicSharedMemorySize, GEMM2_SMEM);
        cudaFuncSetAttribute(k_text_rec_tc,
                             cudaFuncAttributeMaxDynamicSharedMemorySize, TCR_SMEM);
        cudaFuncSetAttribute((const void*)k_gru_pool<HH, ND, 1>,
                             cudaFuncAttributeMaxDynamicSharedMemorySize, smem_gru64);
        cudaFuncSetAttribute((const void*)k_gru_pool<FP, ND, 0>,
                             cudaFuncAttributeMaxDynamicSharedMemorySize, smem_gru3);
        init_done = true;
    }

    // sequential launches (R14-proven order)
    k_gemm_tf32<<<dim3(10, NS), 256, GEMM2_SMEM>>>(text, tg_Wih, tg_bih);
    k_text_rec_tc<<<NS, TCR_THREADS, TCR_SMEM>>>(tg_Whh, tg_bhh);
    k_text_pool<<<NS * ND, 256>>>(ta_W);
    k_gru_pool<HH, ND, 1><<<NS, 192, smem_gru64>>>(nullptr, sg_Wih, sg_Whh, sg_bih, sg_bhh, sa_W);
    k_gru_pool<FP, ND, 0><<<NS, 192, smem_gru3>>>(price, pg_Wih, pg_Whh, pg_bih, pg_bhh, pa_W);
    k_bilinear<<<dim3(HH, NS), 128>>>(bil_B, bil_b);
    k_gat_proj<<<dim3(NS, NHD), 64>>>(gat_W, gat_a);
    k_gat_attn<<<dim3(NS, NHD), 128>>>(adj);
    k_final<<<1, 128>>>(bl_W, bl_b, out_W, out_a, adj, label, (float*)d_out, out_size);
}